// round 1
// baseline (speedup 1.0000x reference)
#include <cuda_runtime.h>
#include <cuda_bf16.h>

#define NB  8
#define SEQ 2048
#define DIM 768
#define MTOT (NB*SEQ)          // 16384
#define INV_SCALE 0.03608439182435161f   // 1/sqrt(768)

// ---------------- static device scratch (allocation-free) ----------------
__device__ float g_Q[(long long)MTOT*DIM];        // Q/sqrt(D) (pre-scaled)
__device__ float g_K[(long long)MTOT*DIM];
__device__ float g_V[(long long)MTOT*DIM];
__device__ float g_P[(long long)NB*SEQ*SEQ];      // exp(scores)*mask, 134 MB
__device__ float g_Zpart[(long long)MTOT*16];     // row-sum partials per k-tile
__device__ float g_invZ[MTOT];
__device__ float g_c[NB*SEQ];                     // column sums of softmax weights
__device__ float g_outpart[NB*32*DIM];

// ---------------- tf32 helpers ----------------
__device__ __forceinline__ unsigned f2tf(float f){
    unsigned u; asm("cvt.rna.tf32.f32 %0, %1;" : "=r"(u) : "f"(f)); return u;
}

__device__ __forceinline__ void mma8(float* c, const unsigned* a, const unsigned* b){
    asm volatile("mma.sync.aligned.m16n8k8.row.col.f32.tf32.tf32.f32 "
        "{%0,%1,%2,%3},{%4,%5,%6,%7},{%8,%9},{%0,%1,%2,%3};"
        : "+f"(c[0]),"+f"(c[1]),"+f"(c[2]),"+f"(c[3])
        : "r"(a[0]),"r"(a[1]),"r"(a[2]),"r"(a[3]),"r"(b[0]),"r"(b[1]));
}

#define SLD 129   // 128 + 1 pad -> conflict-free transpose stores

// Load a 128x32 fp32 tile (row-major, leading dim ld) into smem as [k][m], tf32-converted.
__device__ __forceinline__ void load_tile(unsigned* s, const float* __restrict__ g,
                                          int rowBase, int k0, int ld){
    int t = threadIdx.x;
#pragma unroll
    for (int i=0;i<4;i++){
        int v = t + i*256;
        int m = v>>3, kv = v&7;
        const float4 f = *(const float4*)(g + (long long)(rowBase+m)*ld + (k0 + kv*4));
        int kk = kv*4;
        s[(kk+0)*SLD + m] = f2tf(f.x);
        s[(kk+1)*SLD + m] = f2tf(f.y);
        s[(kk+2)*SLD + m] = f2tf(f.z);
        s[(kk+3)*SLD + m] = f2tf(f.w);
    }
}

// ---------------- kernel 1: QKV projections (C = X @ W^T + b) ----------------
__global__ void __launch_bounds__(256,2) qkv_kernel(
    const float* __restrict__ x,
    const float* __restrict__ Wq, const float* __restrict__ bq,
    const float* __restrict__ Wk, const float* __restrict__ bk,
    const float* __restrict__ Wv, const float* __restrict__ bv)
{
    __shared__ unsigned sA[32*SLD];
    __shared__ unsigned sB[32*SLD];

    int proj = blockIdx.z;
    const float* W    = proj==0 ? Wq : (proj==1 ? Wk : Wv);
    const float* bias = proj==0 ? bq : (proj==1 ? bk : bv);
    float* out        = proj==0 ? g_Q : (proj==1 ? g_K : g_V);
    float scale       = proj==0 ? INV_SCALE : 1.0f;   // fold 1/sqrt(D) into Q

    int mBase = blockIdx.y*128;
    int nBase = blockIdx.x*128;
    int lane = threadIdx.x & 31, warp = threadIdx.x >> 5;
    int wm = warp & 1, wn = warp >> 1;          // 2 x 4 warp grid
    int gq = lane >> 2, tig = lane & 3;

    float acc[4][4][4] = {};
    for (int k0=0;k0<DIM;k0+=32){
        load_tile(sA, x, mBase, k0, DIM);
        load_tile(sB, W, nBase, k0, DIM);
        __syncthreads();
#pragma unroll
        for (int kk=0;kk<32;kk+=8){
            unsigned a[4][4], bf[4][2];
#pragma unroll
            for (int mf=0;mf<4;mf++){
                int m = wm*64 + mf*16 + gq;
                a[mf][0]=sA[(kk+tig)*SLD+m];
                a[mf][1]=sA[(kk+tig)*SLD+m+8];
                a[mf][2]=sA[(kk+tig+4)*SLD+m];
                a[mf][3]=sA[(kk+tig+4)*SLD+m+8];
            }
#pragma unroll
            for (int nf=0;nf<4;nf++){
                int n = wn*32 + nf*8 + gq;
                bf[nf][0]=sB[(kk+tig)*SLD+n];
                bf[nf][1]=sB[(kk+tig+4)*SLD+n];
            }
#pragma unroll
            for (int mf=0;mf<4;mf++)
#pragma unroll
                for (int nf=0;nf<4;nf++)
                    mma8(acc[mf][nf], a[mf], bf[nf]);
        }
        __syncthreads();
    }
#pragma unroll
    for (int mf=0;mf<4;mf++){
#pragma unroll
        for (int nf=0;nf<4;nf++){
            int row = mBase + wm*64 + mf*16 + gq;
            int col = nBase + wn*32 + nf*8 + tig*2;
            float b0 = bias[col], b1 = bias[col+1];
            float2 v0 = make_float2((acc[mf][nf][0]+b0)*scale, (acc[mf][nf][1]+b1)*scale);
            float2 v1 = make_float2((acc[mf][nf][2]+b0)*scale, (acc[mf][nf][3]+b1)*scale);
            *(float2*)(out + (long long)row*DIM + col)     = v0;
            *(float2*)(out + (long long)(row+8)*DIM + col) = v1;
        }
    }
}

// -------- kernel 2: scores = Q@K^T (pre-scaled), P = mask*exp(s), row-sum partials --------
__global__ void __launch_bounds__(256,2) scores_kernel(const int* __restrict__ mask)
{
    __shared__ unsigned sA[32*SLD];
    __shared__ unsigned sB[32*SLD];
    __shared__ int   sMask[128];
    __shared__ float sRow[128*4];

    int b = blockIdx.z;
    int mBase = blockIdx.y*128;   // query rows
    int nBase = blockIdx.x*128;   // key cols
    const float* Q = g_Q + (long long)b*SEQ*DIM;
    const float* K = g_K + (long long)b*SEQ*DIM;

    if (threadIdx.x < 128) sMask[threadIdx.x] = mask[b*SEQ + nBase + threadIdx.x];

    int lane = threadIdx.x & 31, warp = threadIdx.x >> 5;
    int wm = warp & 1, wn = warp >> 1;
    int gq = lane >> 2, tig = lane & 3;

    float acc[4][4][4] = {};
    for (int k0=0;k0<DIM;k0+=32){
        load_tile(sA, Q, mBase, k0, DIM);
        load_tile(sB, K, nBase, k0, DIM);
        __syncthreads();
#pragma unroll
        for (int kk=0;kk<32;kk+=8){
            unsigned a[4][4], bf[4][2];
#pragma unroll
            for (int mf=0;mf<4;mf++){
                int m = wm*64 + mf*16 + gq;
                a[mf][0]=sA[(kk+tig)*SLD+m];
                a[mf][1]=sA[(kk+tig)*SLD+m+8];
                a[mf][2]=sA[(kk+tig+4)*SLD+m];
                a[mf][3]=sA[(kk+tig+4)*SLD+m+8];
            }
#pragma unroll
            for (int nf=0;nf<4;nf++){
                int n = wn*32 + nf*8 + gq;
                bf[nf][0]=sB[(kk+tig)*SLD+n];
                bf[nf][1]=sB[(kk+tig+4)*SLD+n];
            }
#pragma unroll
            for (int mf=0;mf<4;mf++)
#pragma unroll
                for (int nf=0;nf<4;nf++)
                    mma8(acc[mf][nf], a[mf], bf[nf]);
        }
        __syncthreads();
    }

    float* P = g_P + (long long)b*SEQ*SEQ;
    float rlo[4]={0,0,0,0}, rhi[4]={0,0,0,0};
#pragma unroll
    for (int mf=0;mf<4;mf++){
#pragma unroll
        for (int nf=0;nf<4;nf++){
            int rowl = wm*64 + mf*16 + gq;
            int coll = wn*32 + nf*8 + tig*2;
            int m0 = sMask[coll], m1 = sMask[coll+1];
            float p0 = m0 ? __expf(acc[mf][nf][0]) : 0.f;
            float p1 = m1 ? __expf(acc[mf][nf][1]) : 0.f;
            float p2 = m0 ? __expf(acc[mf][nf][2]) : 0.f;
            float p3 = m1 ? __expf(acc[mf][nf][3]) : 0.f;
            int q = mBase + rowl;
            int c = nBase + coll;
            *(float2*)(P + (long long)q*SEQ + c)     = make_float2(p0,p1);
            *(float2*)(P + (long long)(q+8)*SEQ + c) = make_float2(p2,p3);
            rlo[mf] += p0+p1; rhi[mf] += p2+p3;
        }
    }
    // reduce row sums across the 4 lanes sharing a row (tig), then across warp_n via smem
#pragma unroll
    for (int mf=0;mf<4;mf++){
        float x0 = rlo[mf];
        x0 += __shfl_xor_sync(0xffffffffu, x0, 1);
        x0 += __shfl_xor_sync(0xffffffffu, x0, 2);
        float x1 = rhi[mf];
        x1 += __shfl_xor_sync(0xffffffffu, x1, 1);
        x1 += __shfl_xor_sync(0xffffffffu, x1, 2);
        if (tig==0){
            sRow[(wm*64+mf*16+gq)*4   + wn] = x0;
            sRow[(wm*64+mf*16+gq+8)*4 + wn] = x1;
        }
    }
    __syncthreads();
    if (threadIdx.x < 128){
        float z = sRow[threadIdx.x*4] + sRow[threadIdx.x*4+1]
                + sRow[threadIdx.x*4+2] + sRow[threadIdx.x*4+3];
        g_Zpart[(long long)(b*SEQ + mBase + threadIdx.x)*16 + blockIdx.x] = z;
    }
}

// ---------------- kernel 3: Z reduce (deterministic) ----------------
__global__ void zred_kernel(){
    int i = blockIdx.x*256 + threadIdx.x;
    if (i < MTOT){
        float s = 0.f;
#pragma unroll
        for (int t=0;t<16;t++) s += g_Zpart[(long long)i*16+t];
        g_invZ[i] = 1.0f/s;
    }
}

// ---------------- kernel 4: column sums c[b,k] = sum_q P[q,k]/Z_q ----------------
__global__ void __launch_bounds__(256) colsum_kernel(){
    int b  = blockIdx.y;
    int k0 = blockIdx.x*64;
    int t  = threadIdx.x;
    int col = t & 63, qo = t >> 6;
    const float* P  = g_P + (long long)b*SEQ*SEQ;
    const float* iz = g_invZ + b*SEQ;
    float acc = 0.f;
    for (int q=qo; q<SEQ; q+=4)
        acc += P[(long long)q*SEQ + k0 + col] * iz[q];
    __shared__ float s[4][64];
    s[qo][col] = acc;
    __syncthreads();
    if (t < 64)
        g_c[b*SEQ + k0 + t] = s[0][t]+s[1][t]+s[2][t]+s[3][t];
}

// ---------------- kernel 5: partial out = c @ V ----------------
__global__ void __launch_bounds__(256) cv_kernel(){
    int b  = blockIdx.y;
    int kc = blockIdx.x*64;
    __shared__ float sc[64];
    if (threadIdx.x < 64) sc[threadIdx.x] = g_c[b*SEQ + kc + threadIdx.x];
    __syncthreads();
    const float* V = g_V + (long long)(b*SEQ + kc)*DIM;
    int o = threadIdx.x;
    float a0=0.f,a1=0.f,a2=0.f;
    for (int k=0;k<64;k++){
        float cv = sc[k];
        const float* vr = V + (long long)k*DIM;
        a0 += cv*vr[o]; a1 += cv*vr[o+256]; a2 += cv*vr[o+512];
    }
    float* op = g_outpart + ((long long)b*32 + blockIdx.x)*DIM;
    op[o]=a0; op[o+256]=a1; op[o+512]=a2;
}

// ---------------- kernel 6: final reduce + mean over queries ----------------
__global__ void final_kernel(float* __restrict__ out){
    int b = blockIdx.x, o = threadIdx.x;
    float s = 0.f;
#pragma unroll
    for (int cch=0;cch<32;cch++) s += g_outpart[((long long)b*32+cch)*DIM + o];
    out[b*DIM + o] = s * (1.0f/(float)SEQ);
}

// ---------------- launch ----------------
extern "C" void kernel_launch(void* const* d_in, const int* in_sizes, int n_in,
                              void* d_out, int out_size){
    const float* x    = (const float*)d_in[0];
    const int*   mask = (const int*)  d_in[1];
    const float* Wq   = (const float*)d_in[2];
    const float* bq   = (const float*)d_in[3];
    const float* Wk   = (const float*)d_in[4];
    const float* bk   = (const float*)d_in[5];
    const float* Wv   = (const float*)d_in[6];
    const float* bv   = (const float*)d_in[7];
    float* out = (float*)d_out;

    qkv_kernel   <<<dim3(6,128,3), 256>>>(x, Wq,bq, Wk,bk, Wv,bv);
    scores_kernel<<<dim3(16,16,8), 256>>>(mask);
    zred_kernel  <<<64, 256>>>();
    colsum_kernel<<<dim3(32,8), 256>>>();
    cv_kernel    <<<dim3(32,8), 256>>>();
    final_kernel <<<8, 768>>>(out);
}

// round 5
// speedup vs baseline: 2.4834x; 2.4834x over previous
#include <cuda_runtime.h>
#include <cuda_bf16.h>
#include <cstdint>

#define NB 8
#define SEQ 2048
#define DIM 768
#define MTOT (NB*SEQ)                    // 16384
#define INV_SCALE 0.03608439182435161f   // 1/sqrt(768)

#define TM 128
#define TN 256
#define TK 32
#define KT (DIM/TK)                      // 24

#define RS  36                           // smem row stride, words (32 data + 4 pad)
#define RSB (RS*4)                       // 144 bytes
#define A_BYTES (TM*RSB)                 // 18432
#define B_BYTES (TN*RSB)                 // 36864
#define STAGE_BYTES (A_BYTES + B_BYTES)  // 55296
#define NSTAGE 3
#define SMEM_DYN (NSTAGE*STAGE_BYTES)    // 165888

// ---------------- static device scratch (allocation-free) ----------------
__device__ float g_Q [(size_t)MTOT*DIM];
__device__ float g_Kc[(size_t)MTOT*DIM];        // compacted (unmasked) K rows
__device__ float g_Vc[(size_t)MTOT*DIM];        // compacted V rows
__device__ float g_xr[(size_t)MTOT*DIM];        // x rounded to tf32 (RNA)
__device__ float g_Wr[3][DIM*DIM];              // Wq,Wk,Wv rounded to tf32
__device__ __nv_bfloat16 g_P[(size_t)NB*SEQ*SEQ]; // P[q][kcol] (compact cols)
__device__ float g_Zpart[(size_t)MTOT*8];
__device__ float g_invZ[MTOT];
__device__ float g_c[NB*SEQ];
__device__ float g_outpart[NB*32*DIM];
__device__ int   g_idx[NB*SEQ];
__device__ int   g_cnt[NB];

// ---------------- helpers ----------------
__device__ __forceinline__ uint32_t smem_u32(const void* p){
    uint32_t a;
    asm("{ .reg .u64 t; cvta.to.shared.u64 t, %1; cvt.u32.u64 %0, t; }" : "=r"(a) : "l"(p));
    return a;
}
__device__ __forceinline__ float rna(float f){
    unsigned u; asm("cvt.rna.tf32.f32 %0, %1;" : "=r"(u) : "f"(f));
    return __uint_as_float(u);
}
__device__ __forceinline__ void cp16(uint32_t d, const void* s){
    asm volatile("cp.async.cg.shared.global [%0], [%1], 16;\n" :: "r"(d), "l"(s));
}
__device__ __forceinline__ void cp_commit(){ asm volatile("cp.async.commit_group;\n" ::); }
template<int N> __device__ __forceinline__ void cp_wait(){
    asm volatile("cp.async.wait_group %0;\n" :: "n"(N));
}
__device__ __forceinline__ void ldsm4(uint32_t addr, uint32_t* r){
    asm volatile("ldmatrix.sync.aligned.m8n8.x4.shared.b16 {%0,%1,%2,%3}, [%4];\n"
        : "=r"(r[0]), "=r"(r[1]), "=r"(r[2]), "=r"(r[3]) : "r"(addr));
}
__device__ __forceinline__ void mma_tf32(float* c, const uint32_t* a, uint32_t b0, uint32_t b1){
    asm volatile("mma.sync.aligned.m16n8k8.row.col.f32.tf32.tf32.f32 "
        "{%0,%1,%2,%3},{%4,%5,%6,%7},{%8,%9},{%0,%1,%2,%3};\n"
        : "+f"(c[0]), "+f"(c[1]), "+f"(c[2]), "+f"(c[3])
        : "r"(a[0]), "r"(a[1]), "r"(a[2]), "r"(a[3]), "r"(b0), "r"(b1));
}

// ---------------- shared GEMM core (128x256 CTA tile, tf32) ----------------
__device__ __forceinline__ void issue_stage(uint32_t sb, int s, int k0,
        const float* const* rowA, const float* const* rowB, int t){
    uint32_t base = sb + s*STAGE_BYTES;
#pragma unroll
    for (int j=0;j<4;j++){                       // A: 1024 16B chunks
        int ci = t + j*256; int r = ci>>3, c = ci&7;
        cp16(base + r*RSB + c*16, rowA[r] + k0 + c*4);
    }
    uint32_t bb = base + A_BYTES;
#pragma unroll
    for (int j=0;j<8;j++){                       // B: 2048 16B chunks
        int ci = t + j*256; int r = ci>>3, c = ci&7;
        cp16(bb + r*RSB + c*16, rowB[r] + k0 + c*4);
    }
    cp_commit();
}

__device__ __forceinline__ void compute_stage(uint32_t sb, int s, int wm, int wn,
        uint32_t laneoff, float acc[4][8][4]){
    uint32_t aT = sb + s*STAGE_BYTES + wm*64*RSB + laneoff;
    uint32_t bT = sb + s*STAGE_BYTES + A_BYTES + wn*64*RSB + laneoff;
#pragma unroll
    for (int kk=0; kk<4; kk++){
        uint32_t a[4][4], bb[4][4];
#pragma unroll
        for (int mf=0;mf<4;mf++) ldsm4(aT + mf*16*RSB + kk*32, a[mf]);
#pragma unroll
        for (int nf=0;nf<4;nf++) ldsm4(bT + nf*16*RSB + kk*32, bb[nf]);
#pragma unroll
        for (int mf=0;mf<4;mf++)
#pragma unroll
            for (int nf=0;nf<4;nf++){
                mma_tf32(acc[mf][2*nf],   a[mf], bb[nf][0], bb[nf][2]);
                mma_tf32(acc[mf][2*nf+1], a[mf], bb[nf][1], bb[nf][3]);
            }
    }
}

__device__ __forceinline__ void gemm_main(uint32_t sb, const float* const* rowA,
        const float* const* rowB, int t, int wm, int wn, uint32_t laneoff,
        float acc[4][8][4]){
    issue_stage(sb, 0, 0,  rowA, rowB, t);
    issue_stage(sb, 1, TK, rowA, rowB, t);
#pragma unroll 1
    for (int it=0; it<KT; ++it){
        if (it < KT-1) cp_wait<1>(); else cp_wait<0>();
        __syncthreads();
        if (it+2 < KT) issue_stage(sb, (it+2)%NSTAGE, (it+2)*TK, rowA, rowB, t);
        compute_stage(sb, it%NSTAGE, wm, wn, laneoff, acc);
    }
}

// ---------------- kernel A: tf32 pre-rounding ----------------
__global__ void round_k(const float* __restrict__ x, const float* __restrict__ Wq,
                        const float* __restrict__ Wk, const float* __restrict__ Wv){
    size_t i = ((size_t)blockIdx.x*256 + threadIdx.x)*4;
    if (i < (size_t)MTOT*DIM){
        float4 v = *(const float4*)(x+i);
        v.x=rna(v.x); v.y=rna(v.y); v.z=rna(v.z); v.w=rna(v.w);
        *(float4*)(g_xr+i) = v;
    }
    if (i < (size_t)DIM*DIM){
        float4 q = *(const float4*)(Wq+i);
        q.x=rna(q.x); q.y=rna(q.y); q.z=rna(q.z); q.w=rna(q.w);
        *(float4*)(&g_Wr[0][i]) = q;
        float4 k = *(const float4*)(Wk+i);
        k.x=rna(k.x); k.y=rna(k.y); k.z=rna(k.z); k.w=rna(k.w);
        *(float4*)(&g_Wr[1][i]) = k;
        float4 w = *(const float4*)(Wv+i);
        w.x=rna(w.x); w.y=rna(w.y); w.z=rna(w.z); w.w=rna(w.w);
        *(float4*)(&g_Wr[2][i]) = w;
    }
}

// ---------------- kernel B: mask prefix-scan -> compact index list ----------------
__global__ void prep_k(const int* __restrict__ mask){
    int b = blockIdx.x, t = threadIdx.x;
    __shared__ int sm[SEQ];
    __shared__ int ws[8];
    for (int i=t;i<SEQ;i+=256) sm[i] = mask[b*SEQ+i];
    __syncthreads();
    int base_i = t*8;
    int loc[8], s=0;
#pragma unroll
    for (int j=0;j<8;j++){ loc[j]=s; s += sm[base_i+j]; }
    int lane = t&31, w = t>>5;
    int v = s;
#pragma unroll
    for (int off=1; off<32; off<<=1){
        int n = __shfl_up_sync(0xffffffffu, v, off);
        if (lane >= off) v += n;
    }
    if (lane==31) ws[w] = v;
    __syncthreads();
    int wbase = 0;
#pragma unroll
    for (int i=0;i<8;i++) if (i<w) wbase += ws[i];
    int excl = wbase + v - s;
#pragma unroll
    for (int j=0;j<8;j++)
        if (sm[base_i+j]) g_idx[b*SEQ + excl + loc[j]] = base_i+j;
    if (t==255) g_cnt[b] = wbase + v;
}

// ---------------- kernel C: Q projection (all rows) ----------------
__global__ void __launch_bounds__(256,1) qproj_k(const float* __restrict__ bq){
    extern __shared__ __align__(16) char dsm[];
    __shared__ const float* rowA[TM];
    __shared__ const float* rowB[TN];
    uint32_t sb = smem_u32(dsm);
    int t = threadIdx.x, L = t&31, w = t>>5;
    int wm = w&1, wn = w>>1;
    int mBase = blockIdx.y*TM, nBase = blockIdx.x*TN;
    if (t < TM) rowA[t] = g_xr + (size_t)(mBase+t)*DIM;
    if (t < TN) rowB[t] = g_Wr[0] + (size_t)(nBase+t)*DIM;
    __syncthreads();
    uint32_t laneoff = (L&15)*RSB + ((L>>4)&1)*16;
    float acc[4][8][4] = {};
    gemm_main(sb, rowA, rowB, t, wm, wn, laneoff, acc);
    int gq = L>>2, tig = L&3;
#pragma unroll
    for (int mf=0;mf<4;mf++){
        int r0 = mBase + wm*64 + mf*16 + gq;
#pragma unroll
        for (int j=0;j<8;j++){
            int col = nBase + wn*64 + j*8 + tig*2;
            float b0 = bq[col], b1 = bq[col+1];
            float2 v0 = make_float2(rna((acc[mf][j][0]+b0)*INV_SCALE),
                                    rna((acc[mf][j][1]+b1)*INV_SCALE));
            float2 v1 = make_float2(rna((acc[mf][j][2]+b0)*INV_SCALE),
                                    rna((acc[mf][j][3]+b1)*INV_SCALE));
            *(float2*)&g_Q[(size_t)r0*DIM + col]     = v0;
            *(float2*)&g_Q[(size_t)(r0+8)*DIM + col] = v1;
        }
    }
}

// ---------------- kernel D: K/V projection on compacted rows ----------------
__global__ void __launch_bounds__(256,1) kvproj_k(const float* __restrict__ bk,
                                                  const float* __restrict__ bv){
    int b = blockIdx.z & 7, proj = blockIdx.z >> 3;   // proj: 0=K, 1=V
    int cnt = g_cnt[b];
    int cntp = ((cnt + 255) >> 8) << 8;
    int mBase = blockIdx.y*TM;
    if (mBase >= cntp) return;
    extern __shared__ __align__(16) char dsm[];
    __shared__ const float* rowA[TM];
    __shared__ const float* rowB[TN];
    uint32_t sb = smem_u32(dsm);
    int t = threadIdx.x, L = t&31, w = t>>5;
    int wm = w&1, wn = w>>1;
    int nBase = blockIdx.x*TN;
    if (t < TM){
        int j = mBase + t; if (j >= cnt) j = cnt-1;
        rowA[t] = g_xr + ((size_t)b*SEQ + g_idx[b*SEQ + j])*DIM;
    }
    if (t < TN) rowB[t] = g_Wr[1+proj] + (size_t)(nBase+t)*DIM;
    __syncthreads();
    uint32_t laneoff = (L&15)*RSB + ((L>>4)&1)*16;
    float acc[4][8][4] = {};
    gemm_main(sb, rowA, rowB, t, wm, wn, laneoff, acc);
    const float* bias = proj ? bv : bk;
    float* out = (proj ? g_Vc : g_Kc) + (size_t)b*SEQ*DIM;
    int gq = L>>2, tig = L&3;
#pragma unroll
    for (int mf=0;mf<4;mf++){
        int r0 = mBase + wm*64 + mf*16 + gq;
#pragma unroll
        for (int j=0;j<8;j++){
            int col = nBase + wn*64 + j*8 + tig*2;
            float b0 = bias[col], b1 = bias[col+1];
            float x0 = acc[mf][j][0]+b0, x1 = acc[mf][j][1]+b1;
            float x2 = acc[mf][j][2]+b0, x3 = acc[mf][j][3]+b1;
            if (!proj){ x0=rna(x0); x1=rna(x1); x2=rna(x2); x3=rna(x3); } // K feeds tf32 GEMM
            *(float2*)&out[(size_t)r0*DIM + col]     = make_float2(x0,x1);
            *(float2*)&out[(size_t)(r0+8)*DIM + col] = make_float2(x2,x3);
        }
    }
}

// ---------------- kernel E: scores + exp + mask + Z partials ----------------
__global__ void __launch_bounds__(256,1) scores_k(){
    int b = blockIdx.z;
    int cnt = g_cnt[b];
    int cntp = ((cnt + 255) >> 8) << 8;
    int nBase = blockIdx.x*TN;
    if (nBase >= cntp) return;
    int mBase = blockIdx.y*TM;
    extern __shared__ __align__(16) char dsm[];
    __shared__ const float* rowA[TM];
    __shared__ const float* rowB[TN];
    __shared__ float sRow[TM*4];
    uint32_t sb = smem_u32(dsm);
    int t = threadIdx.x, L = t&31, w = t>>5;
    int wm = w&1, wn = w>>1;
    if (t < TM) rowA[t] = g_Q  + ((size_t)b*SEQ + mBase + t)*DIM;
    if (t < TN) rowB[t] = g_Kc + ((size_t)b*SEQ + nBase + t)*DIM;
    __syncthreads();
    uint32_t laneoff = (L&15)*RSB + ((L>>4)&1)*16;
    float acc[4][8][4] = {};
    gemm_main(sb, rowA, rowB, t, wm, wn, laneoff, acc);

    int gq = L>>2, tig = L&3;
    __nv_bfloat16* P = g_P + (size_t)b*SEQ*SEQ;
    float zl[4] = {0,0,0,0}, zh[4] = {0,0,0,0};
#pragma unroll
    for (int mf=0;mf<4;mf++){
        int q0 = mBase + wm*64 + mf*16 + gq;
#pragma unroll
        for (int j=0;j<8;j++){
            int kcol = nBase + wn*64 + j*8 + tig*2;
            float p0 = (kcol   < cnt) ? __expf(acc[mf][j][0]) : 0.f;
            float p1 = (kcol+1 < cnt) ? __expf(acc[mf][j][1]) : 0.f;
            float p2 = (kcol   < cnt) ? __expf(acc[mf][j][2]) : 0.f;
            float p3 = (kcol+1 < cnt) ? __expf(acc[mf][j][3]) : 0.f;
            *(__nv_bfloat162*)&P[(size_t)q0*SEQ + kcol]     = __floats2bfloat162_rn(p0,p1);
            *(__nv_bfloat162*)&P[(size_t)(q0+8)*SEQ + kcol] = __floats2bfloat162_rn(p2,p3);
            zl[mf] += p0+p1; zh[mf] += p2+p3;
        }
    }
#pragma unroll
    for (int mf=0;mf<4;mf++){
        float x0 = zl[mf];
        x0 += __shfl_xor_sync(0xffffffffu, x0, 1);
        x0 += __shfl_xor_sync(0xffffffffu, x0, 2);
        float x1 = zh[mf];
        x1 += __shfl_xor_sync(0xffffffffu, x1, 1);
        x1 += __shfl_xor_sync(0xffffffffu, x1, 2);
        if (tig==0){
            sRow[(wm*64 + mf*16 + gq)*4     + wn] = x0;
            sRow[(wm*64 + mf*16 + gq + 8)*4 + wn] = x1;
        }
    }
    __syncthreads();
    if (t < TM){
        float z = sRow[t*4] + sRow[t*4+1] + sRow[t*4+2] + sRow[t*4+3];
        g_Zpart[((size_t)b*SEQ + mBase + t)*8 + blockIdx.x] = z;
    }
}

// ---------------- kernel F: Z reduce ----------------
__global__ void zred_k(){
    int i = blockIdx.x*256 + threadIdx.x;
    if (i < MTOT){
        int b = i >> 11;
        int nt = (g_cnt[b] + 255) >> 8;
        float s = 0.f;
        for (int j=0;j<nt;j++) s += g_Zpart[(size_t)i*8 + j];
        g_invZ[i] = 1.0f/s;
    }
}

// ---------------- kernel G: c[b,k] = sum_q P[q][k] * invZ[q] ----------------
__global__ void __launch_bounds__(256) colsum_k(){
    int b = blockIdx.y;
    int cnt = g_cnt[b];
    int cntp = ((cnt + 255) >> 8) << 8;
    int k = blockIdx.x*256 + threadIdx.x;
    if (blockIdx.x*256 >= cntp){ g_c[b*SEQ + k] = 0.f; return; }
    __shared__ float sz[SEQ];
    for (int i=threadIdx.x; i<SEQ; i+=256) sz[i] = g_invZ[b*SEQ + i];
    __syncthreads();
    const __nv_bfloat16* P = g_P + (size_t)b*SEQ*SEQ + k;
    float a0=0.f, a1=0.f, a2=0.f, a3=0.f;
#pragma unroll 4
    for (int q=0; q<SEQ; q+=4){
        a0 += __bfloat162float(P[(size_t)(q+0)*SEQ]) * sz[q+0];
        a1 += __bfloat162float(P[(size_t)(q+1)*SEQ]) * sz[q+1];
        a2 += __bfloat162float(P[(size_t)(q+2)*SEQ]) * sz[q+2];
        a3 += __bfloat162float(P[(size_t)(q+3)*SEQ]) * sz[q+3];
    }
    g_c[b*SEQ + k] = (a0+a1)+(a2+a3);
}

// ---------------- kernel H: partial out = c @ Vc ----------------
__global__ void __launch_bounds__(256) cv_k(){
    int b  = blockIdx.y;
    int kc = blockIdx.x*64;
    int cnt = g_cnt[b];
    int cntp = ((cnt + 255) >> 8) << 8;
    float* op = g_outpart + ((size_t)b*32 + blockIdx.x)*DIM;
    int o = threadIdx.x;
    if (kc >= cntp){ op[o]=0.f; op[o+256]=0.f; op[o+512]=0.f; return; }
    __shared__ float sc[64];
    if (threadIdx.x < 64) sc[threadIdx.x] = g_c[b*SEQ + kc + threadIdx.x];
    __syncthreads();
    const float* V = g_Vc + ((size_t)b*SEQ + kc)*DIM;
    float a0=0.f, a1=0.f, a2=0.f;
    for (int k=0;k<64;k++){
        float cv = sc[k];
        const float* vr = V + (size_t)k*DIM;
        a0 += cv*vr[o]; a1 += cv*vr[o+256]; a2 += cv*vr[o+512];
    }
    op[o]=a0; op[o+256]=a1; op[o+512]=a2;
}

// ---------------- kernel I: final reduce + mean ----------------
__global__ void final_k(float* __restrict__ out){
    int b = blockIdx.x, o = threadIdx.x;
    float s = 0.f;
#pragma unroll
    for (int c=0;c<32;c++) s += g_outpart[((size_t)b*32 + c)*DIM + o];
    out[b*DIM + o] = s * (1.0f/(float)SEQ);
}

// ---------------- launch ----------------
extern "C" void kernel_launch(void* const* d_in, const int* in_sizes, int n_in,
                              void* d_out, int out_size){
    const float* x    = (const float*)d_in[0];
    const int*   mask = (const int*)  d_in[1];
    const float* Wq   = (const float*)d_in[2];
    const float* bq   = (const float*)d_in[3];
    const float* Wk   = (const float*)d_in[4];
    const float* bk   = (const float*)d_in[5];
    const float* Wv   = (const float*)d_in[6];
    const float* bv   = (const float*)d_in[7];
    float* out = (float*)d_out;

    cudaFuncSetAttribute(qproj_k,  cudaFuncAttributeMaxDynamicSharedMemorySize, SMEM_DYN);
    cudaFuncSetAttribute(kvproj_k, cudaFuncAttributeMaxDynamicSharedMemorySize, SMEM_DYN);
    cudaFuncSetAttribute(scores_k, cudaFuncAttributeMaxDynamicSharedMemorySize, SMEM_DYN);

    round_k <<<(MTOT*DIM/4 + 255)/256, 256>>>(x, Wq, Wk, Wv);
    prep_k  <<<NB, 256>>>(mask);
    qproj_k <<<dim3(3,128),   256, SMEM_DYN>>>(bq);
    kvproj_k<<<dim3(3,16,16), 256, SMEM_DYN>>>(bk, bv);
    scores_k<<<dim3(8,16,8),  256, SMEM_DYN>>>();
    zred_k  <<<64, 256>>>();
    colsum_k<<<dim3(8,8), 256>>>();
    cv_k    <<<dim3(32,8), 256>>>();
    final_k <<<8, 768>>>(out);
}

// round 6
// speedup vs baseline: 2.8193x; 1.1353x over previous
#include <cuda_runtime.h>
#include <cuda_bf16.h>
#include <cstdint>

#define NB 8
#define SEQ 2048
#define DIM 768
#define MTOT (NB*SEQ)                    // 16384
#define INV_SCALE 0.03608439182435161f   // 1/sqrt(768)

#define TM 128
#define TN 128
#define TK 32
#define KT (DIM/TK)                      // 24

#define RS  36                           // smem row stride, words (32 data + 4 pad)
#define RSB (RS*4)                       // 144 bytes
#define A_BYTES (TM*RSB)                 // 18432
#define B_BYTES (TN*RSB)                 // 18432
#define STAGE_BYTES (A_BYTES + B_BYTES)  // 36864
#define NSTAGE 3
#define PTR_BYTES ((TM+TN)*8)            // 2048: rowA/rowB tables
#define SMEM_DYN (NSTAGE*STAGE_BYTES + PTR_BYTES)   // 112640

// ---------------- static device scratch (allocation-free) ----------------
__device__ float g_Q [(size_t)MTOT*DIM];
__device__ float g_Kc[(size_t)MTOT*DIM];        // compacted (unmasked) K rows
__device__ float g_Vc[(size_t)MTOT*DIM];        // compacted V rows
__device__ float g_xr[(size_t)MTOT*DIM];        // x rounded to tf32 (RNA)
__device__ float g_Wr[3][DIM*DIM];              // Wq,Wk,Wv rounded to tf32
__device__ __nv_bfloat16 g_P[(size_t)NB*SEQ*SEQ]; // P[q][kcol] (compact cols)
__device__ float g_Zpart[(size_t)MTOT*16];
__device__ float g_invZ[MTOT];
__device__ float g_c[NB*SEQ];
__device__ float g_outpart[NB*32*DIM];
__device__ int   g_idx[NB*SEQ];
__device__ int   g_cnt[NB];

// ---------------- helpers ----------------
__device__ __forceinline__ uint32_t smem_u32(const void* p){
    uint32_t a;
    asm("{ .reg .u64 t; cvta.to.shared.u64 t, %1; cvt.u32.u64 %0, t; }" : "=r"(a) : "l"(p));
    return a;
}
__device__ __forceinline__ float rna(float f){
    unsigned u; asm("cvt.rna.tf32.f32 %0, %1;" : "=r"(u) : "f"(f));
    return __uint_as_float(u);
}
__device__ __forceinline__ void cp16(uint32_t d, const void* s){
    asm volatile("cp.async.cg.shared.global [%0], [%1], 16;\n" :: "r"(d), "l"(s));
}
__device__ __forceinline__ void cp_commit(){ asm volatile("cp.async.commit_group;\n" ::); }
template<int N> __device__ __forceinline__ void cp_wait(){
    asm volatile("cp.async.wait_group %0;\n" :: "n"(N));
}
__device__ __forceinline__ void ldsm4(uint32_t addr, uint32_t* r){
    asm volatile("ldmatrix.sync.aligned.m8n8.x4.shared.b16 {%0,%1,%2,%3}, [%4];\n"
        : "=r"(r[0]), "=r"(r[1]), "=r"(r[2]), "=r"(r[3]) : "r"(addr));
}
__device__ __forceinline__ void mma_tf32(float* c, const uint32_t* a, uint32_t b0, uint32_t b1){
    asm volatile("mma.sync.aligned.m16n8k8.row.col.f32.tf32.tf32.f32 "
        "{%0,%1,%2,%3},{%4,%5,%6,%7},{%8,%9},{%0,%1,%2,%3};\n"
        : "+f"(c[0]), "+f"(c[1]), "+f"(c[2]), "+f"(c[3])
        : "r"(a[0]), "r"(a[1]), "r"(a[2]), "r"(a[3]), "r"(b0), "r"(b1));
}

// ---------------- shared GEMM core (128x128 CTA tile, tf32, 2 CTAs/SM) ----------------
// Warps: 2 (m) x 4 (n); warp tile 64x32.
__device__ __forceinline__ void issue_stage(uint32_t sb, int s, int k0,
        const float* const* rowA, const float* const* rowB, int t){
    uint32_t base = sb + s*STAGE_BYTES;
#pragma unroll
    for (int j=0;j<4;j++){                       // A: 1024 16B chunks
        int ci = t + j*256; int r = ci>>3, c = ci&7;
        cp16(base + r*RSB + c*16, rowA[r] + k0 + c*4);
    }
    uint32_t bb = base + A_BYTES;
#pragma unroll
    for (int j=0;j<4;j++){                       // B: 1024 16B chunks
        int ci = t + j*256; int r = ci>>3, c = ci&7;
        cp16(bb + r*RSB + c*16, rowB[r] + k0 + c*4);
    }
    cp_commit();
}

__device__ __forceinline__ void compute_stage(uint32_t sb, int s, int wm, int wn,
        uint32_t laneoff, float acc[4][4][4]){
    uint32_t aT = sb + s*STAGE_BYTES + wm*64*RSB + laneoff;
    uint32_t bT = sb + s*STAGE_BYTES + A_BYTES + wn*32*RSB + laneoff;
#pragma unroll
    for (int kk=0; kk<4; kk++){
        uint32_t a[4][4], bb[2][4];
#pragma unroll
        for (int mf=0;mf<4;mf++) ldsm4(aT + mf*16*RSB + kk*32, a[mf]);
#pragma unroll
        for (int nf=0;nf<2;nf++) ldsm4(bT + nf*16*RSB + kk*32, bb[nf]);
#pragma unroll
        for (int mf=0;mf<4;mf++)
#pragma unroll
            for (int nf=0;nf<2;nf++){
                mma_tf32(acc[mf][2*nf],   a[mf], bb[nf][0], bb[nf][2]);
                mma_tf32(acc[mf][2*nf+1], a[mf], bb[nf][1], bb[nf][3]);
            }
    }
}

__device__ __forceinline__ void gemm_main(uint32_t sb, const float* const* rowA,
        const float* const* rowB, int t, int wm, int wn, uint32_t laneoff,
        float acc[4][4][4]){
    issue_stage(sb, 0, 0,  rowA, rowB, t);
    issue_stage(sb, 1, TK, rowA, rowB, t);
#pragma unroll 1
    for (int it=0; it<KT; ++it){
        if (it < KT-1) cp_wait<1>(); else cp_wait<0>();
        __syncthreads();
        if (it+2 < KT) issue_stage(sb, (it+2)%NSTAGE, (it+2)*TK, rowA, rowB, t);
        compute_stage(sb, it%NSTAGE, wm, wn, laneoff, acc);
    }
}

// ---------------- kernel A: tf32 pre-rounding ----------------
__global__ void round_k(const float* __restrict__ x, const float* __restrict__ Wq,
                        const float* __restrict__ Wk, const float* __restrict__ Wv){
    size_t i = ((size_t)blockIdx.x*256 + threadIdx.x)*4;
    if (i < (size_t)MTOT*DIM){
        float4 v = *(const float4*)(x+i);
        v.x=rna(v.x); v.y=rna(v.y); v.z=rna(v.z); v.w=rna(v.w);
        *(float4*)(g_xr+i) = v;
    }
    if (i < (size_t)DIM*DIM){
        float4 q = *(const float4*)(Wq+i);
        q.x=rna(q.x); q.y=rna(q.y); q.z=rna(q.z); q.w=rna(q.w);
        *(float4*)(&g_Wr[0][i]) = q;
        float4 k = *(const float4*)(Wk+i);
        k.x=rna(k.x); k.y=rna(k.y); k.z=rna(k.z); k.w=rna(k.w);
        *(float4*)(&g_Wr[1][i]) = k;
        float4 w = *(const float4*)(Wv+i);
        w.x=rna(w.x); w.y=rna(w.y); w.z=rna(w.z); w.w=rna(w.w);
        *(float4*)(&g_Wr[2][i]) = w;
    }
}

// ---------------- kernel B: mask prefix-scan -> compact index list ----------------
__global__ void prep_k(const int* __restrict__ mask){
    int b = blockIdx.x, t = threadIdx.x;
    __shared__ int sm[SEQ];
    __shared__ int ws[8];
    for (int i=t;i<SEQ;i+=256) sm[i] = mask[b*SEQ+i];
    __syncthreads();
    int base_i = t*8;
    int loc[8], s=0;
#pragma unroll
    for (int j=0;j<8;j++){ loc[j]=s; s += sm[base_i+j]; }
    int lane = t&31, w = t>>5;
    int v = s;
#pragma unroll
    for (int off=1; off<32; off<<=1){
        int n = __shfl_up_sync(0xffffffffu, v, off);
        if (lane >= off) v += n;
    }
    if (lane==31) ws[w] = v;
    __syncthreads();
    int wbase = 0;
#pragma unroll
    for (int i=0;i<8;i++) if (i<w) wbase += ws[i];
    int excl = wbase + v - s;
#pragma unroll
    for (int j=0;j<8;j++)
        if (sm[base_i+j]) g_idx[b*SEQ + excl + loc[j]] = base_i+j;
    if (t==255) g_cnt[b] = wbase + v;
}

// ---------------- kernel C: fused Q/K/V projections ----------------
// grid = (6, 384): y<128 -> Q (mBase=y*128); 128..255 -> K; 256..383 -> V
__global__ void __launch_bounds__(256,2) proj_k(const float* __restrict__ bq,
        const float* __restrict__ bk, const float* __restrict__ bv){
    extern __shared__ __align__(16) char dsm[];
    uint32_t sb = smem_u32(dsm);
    const float** rowA = (const float**)(dsm + NSTAGE*STAGE_BYTES);
    const float** rowB = rowA + TM;
    int t = threadIdx.x, L = t&31, w = t>>5;
    int wm = w&1, wn = w>>1;
    int y = blockIdx.y;
    int proj = (y < 128) ? 0 : ((y < 256) ? 1 : 2);
    int nBase = blockIdx.x*TN;

    int mBase, b = 0;
    if (proj == 0){
        mBase = y*TM;
    } else {
        int i = y - (proj==1 ? 128 : 256);
        b = i >> 4;
        mBase = (i & 15)*TM;
        int cnt = g_cnt[b];
        int cntp = ((cnt + 127) >> 7) << 7;
        if (mBase >= cntp) return;
    }
    if (t < TM){
        if (proj == 0){
            rowA[t] = g_xr + (size_t)(mBase + t)*DIM;
        } else {
            int cnt = g_cnt[b];
            int j = mBase + t; if (j >= cnt) j = cnt-1;
            rowA[t] = g_xr + ((size_t)b*SEQ + g_idx[b*SEQ + j])*DIM;
        }
    } else {
        rowB[t-TM] = g_Wr[proj] + (size_t)(nBase + (t-TM))*DIM;
    }
    __syncthreads();

    uint32_t laneoff = (L&15)*RSB + ((L>>4)&1)*16;
    float acc[4][4][4] = {};
    gemm_main(sb, rowA, rowB, t, wm, wn, laneoff, acc);

    const float* bias = proj==0 ? bq : (proj==1 ? bk : bv);
    float scale = proj==0 ? INV_SCALE : 1.0f;
    float* out  = proj==0 ? g_Q : ((proj==1 ? g_Kc : g_Vc) + (size_t)b*SEQ*DIM);
    bool doRound = (proj < 2);   // Q and K feed the tf32 scores GEMM
    int gq = L>>2, tig = L&3;
#pragma unroll
    for (int mf=0;mf<4;mf++){
        int r0 = mBase + wm*64 + mf*16 + gq;
#pragma unroll
        for (int j=0;j<4;j++){
            int col = nBase + wn*32 + j*8 + tig*2;
            float b0 = bias[col], b1 = bias[col+1];
            float x0 = (acc[mf][j][0]+b0)*scale, x1 = (acc[mf][j][1]+b1)*scale;
            float x2 = (acc[mf][j][2]+b0)*scale, x3 = (acc[mf][j][3]+b1)*scale;
            if (doRound){ x0=rna(x0); x1=rna(x1); x2=rna(x2); x3=rna(x3); }
            *(float2*)&out[(size_t)r0*DIM + col]     = make_float2(x0,x1);
            *(float2*)&out[(size_t)(r0+8)*DIM + col] = make_float2(x2,x3);
        }
    }
}

// ---------------- kernel D: scores + exp + mask + Z partials ----------------
__global__ void __launch_bounds__(256,2) scores_k(){
    int b = blockIdx.z;
    int cnt = g_cnt[b];
    int cntp = ((cnt + 127) >> 7) << 7;
    int nBase = blockIdx.x*TN;
    if (nBase >= cntp) return;
    int mBase = blockIdx.y*TM;
    extern __shared__ __align__(16) char dsm[];
    uint32_t sb = smem_u32(dsm);
    const float** rowA = (const float**)(dsm + NSTAGE*STAGE_BYTES);
    const float** rowB = rowA + TM;
    float* sRow = (float*)dsm;                  // reused after mainloop
    int t = threadIdx.x, L = t&31, w = t>>5;
    int wm = w&1, wn = w>>1;
    if (t < TM) rowA[t] = g_Q  + ((size_t)b*SEQ + mBase + t)*DIM;
    else        rowB[t-TM] = g_Kc + ((size_t)b*SEQ + nBase + (t-TM))*DIM;
    __syncthreads();
    uint32_t laneoff = (L&15)*RSB + ((L>>4)&1)*16;
    float acc[4][4][4] = {};
    gemm_main(sb, rowA, rowB, t, wm, wn, laneoff, acc);

    int gq = L>>2, tig = L&3;
    __nv_bfloat16* P = g_P + (size_t)b*SEQ*SEQ;
    float zl[4] = {0,0,0,0}, zh[4] = {0,0,0,0};
#pragma unroll
    for (int mf=0;mf<4;mf++){
        int q0 = mBase + wm*64 + mf*16 + gq;
#pragma unroll
        for (int j=0;j<4;j++){
            int kcol = nBase + wn*32 + j*8 + tig*2;
            float p0 = (kcol   < cnt) ? __expf(acc[mf][j][0]) : 0.f;
            float p1 = (kcol+1 < cnt) ? __expf(acc[mf][j][1]) : 0.f;
            float p2 = (kcol   < cnt) ? __expf(acc[mf][j][2]) : 0.f;
            float p3 = (kcol+1 < cnt) ? __expf(acc[mf][j][3]) : 0.f;
            *(__nv_bfloat162*)&P[(size_t)q0*SEQ + kcol]     = __floats2bfloat162_rn(p0,p1);
            *(__nv_bfloat162*)&P[(size_t)(q0+8)*SEQ + kcol] = __floats2bfloat162_rn(p2,p3);
            zl[mf] += p0+p1; zh[mf] += p2+p3;
        }
    }
    __syncthreads();   // stage buffers no longer needed; reuse as sRow
#pragma unroll
    for (int mf=0;mf<4;mf++){
        float x0 = zl[mf];
        x0 += __shfl_xor_sync(0xffffffffu, x0, 1);
        x0 += __shfl_xor_sync(0xffffffffu, x0, 2);
        float x1 = zh[mf];
        x1 += __shfl_xor_sync(0xffffffffu, x1, 1);
        x1 += __shfl_xor_sync(0xffffffffu, x1, 2);
        if (tig==0){
            sRow[(wm*64 + mf*16 + gq)*4     + wn] = x0;
            sRow[(wm*64 + mf*16 + gq + 8)*4 + wn] = x1;
        }
    }
    __syncthreads();
    if (t < TM){
        float z = sRow[t*4] + sRow[t*4+1] + sRow[t*4+2] + sRow[t*4+3];
        g_Zpart[((size_t)b*SEQ + mBase + t)*16 + blockIdx.x] = z;
    }
}

// ---------------- kernel E: Z reduce ----------------
__global__ void zred_k(){
    int i = blockIdx.x*256 + threadIdx.x;
    if (i < MTOT){
        int b = i >> 11;
        int nt = (g_cnt[b] + 127) >> 7;
        float s = 0.f;
        for (int j=0;j<nt;j++) s += g_Zpart[(size_t)i*16 + j];
        g_invZ[i] = 1.0f/s;
    }
}

// ---------------- kernel F: c[b,k] = sum_q P[q][k] * invZ[q] ----------------
__global__ void __launch_bounds__(256) colsum_k(){
    int b = blockIdx.y;
    int cnt = g_cnt[b];
    int cntp = ((cnt + 127) >> 7) << 7;
    int k = blockIdx.x*256 + threadIdx.x;
    if (blockIdx.x*256 >= cntp){ g_c[b*SEQ + k] = 0.f; return; }
    __shared__ float sz[SEQ];
    for (int i=threadIdx.x; i<SEQ; i+=256) sz[i] = g_invZ[b*SEQ + i];
    __syncthreads();
    const __nv_bfloat16* P = g_P + (size_t)b*SEQ*SEQ + k;
    float a0=0.f, a1=0.f, a2=0.f, a3=0.f;
#pragma unroll 4
    for (int q=0; q<SEQ; q+=4){
        a0 += __bfloat162float(P[(size_t)(q+0)*SEQ]) * sz[q+0];
        a1 += __bfloat162float(P[(size_t)(q+1)*SEQ]) * sz[q+1];
        a2 += __bfloat162float(P[(size_t)(q+2)*SEQ]) * sz[q+2];
        a3 += __bfloat162float(P[(size_t)(q+3)*SEQ]) * sz[q+3];
    }
    g_c[b*SEQ + k] = (a0+a1)+(a2+a3);
}

// ---------------- kernel G: partial out = c @ Vc ----------------
__global__ void __launch_bounds__(256) cv_k(){
    int b  = blockIdx.y;
    int kc = blockIdx.x*64;
    int cnt = g_cnt[b];
    int cntp = ((cnt + 127) >> 7) << 7;
    float* op = g_outpart + ((size_t)b*32 + blockIdx.x)*DIM;
    int o = threadIdx.x;
    if (kc >= cntp){ op[o]=0.f; op[o+256]=0.f; op[o+512]=0.f; return; }
    __shared__ float sc[64];
    if (threadIdx.x < 64) sc[threadIdx.x] = g_c[b*SEQ + kc + threadIdx.x];
    __syncthreads();
    const float* V = g_Vc + ((size_t)b*SEQ + kc)*DIM;
    float a0=0.f, a1=0.f, a2=0.f;
    for (int k=0;k<64;k++){
        float cv = sc[k];
        const float* vr = V + (size_t)k*DIM;
        a0 += cv*vr[o]; a1 += cv*vr[o+256]; a2 += cv*vr[o+512];
    }
    op[o]=a0; op[o+256]=a1; op[o+512]=a2;
}

// ---------------- kernel H: final reduce + mean ----------------
__global__ void final_k(float* __restrict__ out){
    int b = blockIdx.x, o = threadIdx.x;
    float s = 0.f;
#pragma unroll
    for (int c=0;c<32;c++) s += g_outpart[((size_t)b*32 + c)*DIM + o];
    out[b*DIM + o] = s * (1.0f/(float)SEQ);
}

// ---------------- launch ----------------
extern "C" void kernel_launch(void* const* d_in, const int* in_sizes, int n_in,
                              void* d_out, int out_size){
    const float* x    = (const float*)d_in[0];
    const int*   mask = (const int*)  d_in[1];
    const float* Wq   = (const float*)d_in[2];
    const float* bq   = (const float*)d_in[3];
    const float* Wk   = (const float*)d_in[4];
    const float* bk   = (const float*)d_in[5];
    const float* Wv   = (const float*)d_in[6];
    const float* bv   = (const float*)d_in[7];
    float* out = (float*)d_out;

    cudaFuncSetAttribute(proj_k,   cudaFuncAttributeMaxDynamicSharedMemorySize, SMEM_DYN);
    cudaFuncSetAttribute(scores_k, cudaFuncAttributeMaxDynamicSharedMemorySize, SMEM_DYN);

    round_k <<<(MTOT*DIM/4 + 255)/256, 256>>>(x, Wq, Wk, Wv);
    prep_k  <<<NB, 256>>>(mask);
    proj_k  <<<dim3(6,384),   256, SMEM_DYN>>>(bq, bk, bv);
    scores_k<<<dim3(16,16,8), 256, SMEM_DYN>>>();
    zred_k  <<<64, 256>>>();
    colsum_k<<<dim3(8,8), 256>>>();
    cv_k    <<<dim3(32,8), 256>>>();
    final_k <<<8, 768>>>(out);
}

// round 7
// speedup vs baseline: 3.7840x; 1.3422x over previous
#include <cuda_runtime.h>
#include <cuda_bf16.h>
#include <cstdint>

#define NB 8
#define SEQ 2048
#define DIM 768
#define MTOT (NB*SEQ)                    // 16384
#define INV_SCALE 0.03608439182435161f   // 1/sqrt(768)

// ---- tf32 proj GEMM tiling ----
#define TM 128
#define TN 128
#define TK 32
#define KT (DIM/TK)                      // 24
#define RS  36
#define RSB (RS*4)                       // 144 bytes
#define A_BYTES (TM*RSB)                 // 18432
#define B_BYTES (TN*RSB)                 // 18432
#define STAGE_BYTES (A_BYTES + B_BYTES)  // 36864
#define NSTAGE 3
#define PTR_BYTES ((TM+TN)*8)
#define SMEM_DYN (NSTAGE*STAGE_BYTES + PTR_BYTES)   // 112640

// ---- bf16 scores GEMM tiling (TK=64 bf16 per stage row) ----
#define TKH 64
#define KTH (DIM/TKH)                    // 12
#define RSH 144                          // 128B data + 16B pad
#define AH_BYTES (TM*RSH)                // 18432
#define STAGE_H (2*AH_BYTES)             // 36864  (same footprint)

#define QS 4                             // colsum q-split

// ---------------- static device scratch (allocation-free) ----------------
__device__ float          g_Vc[(size_t)MTOT*DIM];     // compacted V rows (fp32)
__device__ __nv_bfloat16  g_Qb[(size_t)MTOT*DIM];     // Q bf16 (scaled)
__device__ __nv_bfloat16  g_Kb[(size_t)MTOT*DIM];     // compacted K bf16
__device__ float g_xr[(size_t)MTOT*DIM];              // x rounded to tf32
__device__ float g_Wr[3][DIM*DIM];                    // W rounded to tf32
__device__ __nv_bfloat16 g_P[(size_t)NB*SEQ*SEQ];     // P[q][kcol]
__device__ float g_Zpart[(size_t)MTOT*16];
__device__ float g_invZ[MTOT];
__device__ float g_cpart[NB*QS*SEQ];
__device__ float g_outpart[NB*32*DIM];
__device__ int   g_idx[NB*SEQ];
__device__ int   g_cnt[NB];

// ---------------- helpers ----------------
__device__ __forceinline__ uint32_t smem_u32(const void* p){
    uint32_t a;
    asm("{ .reg .u64 t; cvta.to.shared.u64 t, %1; cvt.u32.u64 %0, t; }" : "=r"(a) : "l"(p));
    return a;
}
__device__ __forceinline__ float rna(float f){
    unsigned u; asm("cvt.rna.tf32.f32 %0, %1;" : "=r"(u) : "f"(f));
    return __uint_as_float(u);
}
__device__ __forceinline__ void cp16(uint32_t d, const void* s){
    asm volatile("cp.async.cg.shared.global [%0], [%1], 16;\n" :: "r"(d), "l"(s));
}
__device__ __forceinline__ void cp_commit(){ asm volatile("cp.async.commit_group;\n" ::); }
template<int N> __device__ __forceinline__ void cp_wait(){
    asm volatile("cp.async.wait_group %0;\n" :: "n"(N));
}
__device__ __forceinline__ void ldsm4(uint32_t addr, uint32_t* r){
    asm volatile("ldmatrix.sync.aligned.m8n8.x4.shared.b16 {%0,%1,%2,%3}, [%4];\n"
        : "=r"(r[0]), "=r"(r[1]), "=r"(r[2]), "=r"(r[3]) : "r"(addr));
}
__device__ __forceinline__ void mma_tf32(float* c, const uint32_t* a, uint32_t b0, uint32_t b1){
    asm volatile("mma.sync.aligned.m16n8k8.row.col.f32.tf32.tf32.f32 "
        "{%0,%1,%2,%3},{%4,%5,%6,%7},{%8,%9},{%0,%1,%2,%3};\n"
        : "+f"(c[0]), "+f"(c[1]), "+f"(c[2]), "+f"(c[3])
        : "r"(a[0]), "r"(a[1]), "r"(a[2]), "r"(a[3]), "r"(b0), "r"(b1));
}
__device__ __forceinline__ void mma_bf16(float* c, const uint32_t* a, uint32_t b0, uint32_t b1){
    asm volatile("mma.sync.aligned.m16n8k16.row.col.f32.bf16.bf16.f32 "
        "{%0,%1,%2,%3},{%4,%5,%6,%7},{%8,%9},{%0,%1,%2,%3};\n"
        : "+f"(c[0]), "+f"(c[1]), "+f"(c[2]), "+f"(c[3])
        : "r"(a[0]), "r"(a[1]), "r"(a[2]), "r"(a[3]), "r"(b0), "r"(b1));
}

// ================= tf32 GEMM core (proj): 128x128 CTA, 2x4 warps, 64x32 tiles =================
__device__ __forceinline__ void issue_stage(uint32_t sb, int s, int k0,
        const float* const* rowA, const float* const* rowB, int t){
    uint32_t base = sb + s*STAGE_BYTES;
#pragma unroll
    for (int j=0;j<4;j++){
        int ci = t + j*256; int r = ci>>3, c = ci&7;
        cp16(base + r*RSB + c*16, rowA[r] + k0 + c*4);
    }
    uint32_t bb = base + A_BYTES;
#pragma unroll
    for (int j=0;j<4;j++){
        int ci = t + j*256; int r = ci>>3, c = ci&7;
        cp16(bb + r*RSB + c*16, rowB[r] + k0 + c*4);
    }
    cp_commit();
}

__device__ __forceinline__ void compute_stage(uint32_t sb, int s, int wm, int wn,
        uint32_t laneoff, float acc[4][4][4]){
    uint32_t aT = sb + s*STAGE_BYTES + wm*64*RSB + laneoff;
    uint32_t bT = sb + s*STAGE_BYTES + A_BYTES + wn*32*RSB + laneoff;
#pragma unroll
    for (int kk=0; kk<4; kk++){
        uint32_t a[4][4], bb[2][4];
#pragma unroll
        for (int mf=0;mf<4;mf++) ldsm4(aT + mf*16*RSB + kk*32, a[mf]);
#pragma unroll
        for (int nf=0;nf<2;nf++) ldsm4(bT + nf*16*RSB + kk*32, bb[nf]);
#pragma unroll
        for (int mf=0;mf<4;mf++)
#pragma unroll
            for (int nf=0;nf<2;nf++){
                mma_tf32(acc[mf][2*nf],   a[mf], bb[nf][0], bb[nf][2]);
                mma_tf32(acc[mf][2*nf+1], a[mf], bb[nf][1], bb[nf][3]);
            }
    }
}

__device__ __forceinline__ void gemm_main(uint32_t sb, const float* const* rowA,
        const float* const* rowB, int t, int wm, int wn, uint32_t laneoff,
        float acc[4][4][4]){
    issue_stage(sb, 0, 0,  rowA, rowB, t);
    issue_stage(sb, 1, TK, rowA, rowB, t);
#pragma unroll 1
    for (int it=0; it<KT; ++it){
        if (it < KT-1) cp_wait<1>(); else cp_wait<0>();
        __syncthreads();
        if (it+2 < KT) issue_stage(sb, (it+2)%NSTAGE, (it+2)*TK, rowA, rowB, t);
        compute_stage(sb, it%NSTAGE, wm, wn, laneoff, acc);
    }
}

// ================= bf16 GEMM core (scores): 128x128 CTA, m16n8k16 =================
__device__ __forceinline__ void issue_stage_h(uint32_t sb, int s, int k0,
        const __nv_bfloat16* const* rowA, const __nv_bfloat16* const* rowB, int t){
    uint32_t base = sb + s*STAGE_H;
#pragma unroll
    for (int j=0;j<4;j++){
        int ci = t + j*256; int r = ci>>3, c = ci&7;
        cp16(base + r*RSH + c*16, rowA[r] + k0 + c*8);
    }
    uint32_t bb = base + AH_BYTES;
#pragma unroll
    for (int j=0;j<4;j++){
        int ci = t + j*256; int r = ci>>3, c = ci&7;
        cp16(bb + r*RSH + c*16, rowB[r] + k0 + c*8);
    }
    cp_commit();
}

__device__ __forceinline__ void compute_stage_h(uint32_t sb, int s, int wm, int wn,
        uint32_t laneA, uint32_t laneB, float acc[4][4][4]){
    uint32_t aT = sb + s*STAGE_H + wm*64*RSH + laneA;
    uint32_t bT = sb + s*STAGE_H + AH_BYTES + wn*32*RSH + laneB;
#pragma unroll
    for (int kk=0; kk<4; kk++){               // 4 x k16
        uint32_t a[4][4], bb[2][4];
#pragma unroll
        for (int mf=0;mf<4;mf++) ldsm4(aT + mf*16*RSH + kk*32, a[mf]);
#pragma unroll
        for (int nf=0;nf<2;nf++) ldsm4(bT + nf*16*RSH + kk*32, bb[nf]);
#pragma unroll
        for (int mf=0;mf<4;mf++)
#pragma unroll
            for (int nf=0;nf<2;nf++){
                mma_bf16(acc[mf][2*nf],   a[mf], bb[nf][0], bb[nf][1]);
                mma_bf16(acc[mf][2*nf+1], a[mf], bb[nf][2], bb[nf][3]);
            }
    }
}

__device__ __forceinline__ void gemm_main_h(uint32_t sb, const __nv_bfloat16* const* rowA,
        const __nv_bfloat16* const* rowB, int t, int wm, int wn,
        uint32_t laneA, uint32_t laneB, float acc[4][4][4]){
    issue_stage_h(sb, 0, 0,   rowA, rowB, t);
    issue_stage_h(sb, 1, TKH, rowA, rowB, t);
#pragma unroll 1
    for (int it=0; it<KTH; ++it){
        if (it < KTH-1) cp_wait<1>(); else cp_wait<0>();
        __syncthreads();
        if (it+2 < KTH) issue_stage_h(sb, (it+2)%NSTAGE, (it+2)*TKH, rowA, rowB, t);
        compute_stage_h(sb, it%NSTAGE, wm, wn, laneA, laneB, acc);
    }
}

// ---------------- kernel A: tf32 pre-rounding ----------------
__global__ void round_k(const float* __restrict__ x, const float* __restrict__ Wq,
                        const float* __restrict__ Wk, const float* __restrict__ Wv){
    size_t i = ((size_t)blockIdx.x*256 + threadIdx.x)*4;
    if (i < (size_t)MTOT*DIM){
        float4 v = *(const float4*)(x+i);
        v.x=rna(v.x); v.y=rna(v.y); v.z=rna(v.z); v.w=rna(v.w);
        *(float4*)(g_xr+i) = v;
    }
    if (i < (size_t)DIM*DIM){
        float4 q = *(const float4*)(Wq+i);
        q.x=rna(q.x); q.y=rna(q.y); q.z=rna(q.z); q.w=rna(q.w);
        *(float4*)(&g_Wr[0][i]) = q;
        float4 k = *(const float4*)(Wk+i);
        k.x=rna(k.x); k.y=rna(k.y); k.z=rna(k.z); k.w=rna(k.w);
        *(float4*)(&g_Wr[1][i]) = k;
        float4 w = *(const float4*)(Wv+i);
        w.x=rna(w.x); w.y=rna(w.y); w.z=rna(w.z); w.w=rna(w.w);
        *(float4*)(&g_Wr[2][i]) = w;
    }
}

// ---------------- kernel B: mask prefix-scan -> compact index list ----------------
__global__ void prep_k(const int* __restrict__ mask){
    int b = blockIdx.x, t = threadIdx.x;
    __shared__ int sm[SEQ];
    __shared__ int ws[8];
    for (int i=t;i<SEQ;i+=256) sm[i] = mask[b*SEQ+i];
    __syncthreads();
    int base_i = t*8;
    int loc[8], s=0;
#pragma unroll
    for (int j=0;j<8;j++){ loc[j]=s; s += sm[base_i+j]; }
    int lane = t&31, w = t>>5;
    int v = s;
#pragma unroll
    for (int off=1; off<32; off<<=1){
        int n = __shfl_up_sync(0xffffffffu, v, off);
        if (lane >= off) v += n;
    }
    if (lane==31) ws[w] = v;
    __syncthreads();
    int wbase = 0;
#pragma unroll
    for (int i=0;i<8;i++) if (i<w) wbase += ws[i];
    int excl = wbase + v - s;
#pragma unroll
    for (int j=0;j<8;j++)
        if (sm[base_i+j]) g_idx[b*SEQ + excl + loc[j]] = base_i+j;
    if (t==255) g_cnt[b] = wbase + v;
}

// ---------------- kernel C: fused Q/K/V projections (tf32 in, bf16/f32 out) --------
// grid = (6, 384): y<128 -> Q; 128..255 -> K; 256..383 -> V
__global__ void __launch_bounds__(256,2) proj_k(const float* __restrict__ bq,
        const float* __restrict__ bk, const float* __restrict__ bv){
    extern __shared__ __align__(16) char dsm[];
    uint32_t sb = smem_u32(dsm);
    const float** rowA = (const float**)(dsm + NSTAGE*STAGE_BYTES);
    const float** rowB = rowA + TM;
    int t = threadIdx.x, L = t&31, w = t>>5;
    int wm = w&1, wn = w>>1;
    int y = blockIdx.y;
    int proj = (y < 128) ? 0 : ((y < 256) ? 1 : 2);
    int nBase = blockIdx.x*TN;

    int mBase, b = 0;
    if (proj == 0){
        mBase = y*TM;
    } else {
        int i = y - (proj==1 ? 128 : 256);
        b = i >> 4;
        mBase = (i & 15)*TM;
        int cnt = g_cnt[b];
        int cntp = ((cnt + 127) >> 7) << 7;
        if (mBase >= cntp) return;
    }
    if (t < TM){
        if (proj == 0){
            rowA[t] = g_xr + (size_t)(mBase + t)*DIM;
        } else {
            int cnt = g_cnt[b];
            int j = mBase + t; if (j >= cnt) j = cnt-1;
            rowA[t] = g_xr + ((size_t)b*SEQ + g_idx[b*SEQ + j])*DIM;
        }
    } else {
        rowB[t-TM] = g_Wr[proj] + (size_t)(nBase + (t-TM))*DIM;
    }
    __syncthreads();

    uint32_t laneoff = (L&15)*RSB + ((L>>4)&1)*16;
    float acc[4][4][4] = {};
    gemm_main(sb, rowA, rowB, t, wm, wn, laneoff, acc);

    const float* bias = proj==0 ? bq : (proj==1 ? bk : bv);
    float scale = proj==0 ? INV_SCALE : 1.0f;
    int gq = L>>2, tig = L&3;
    if (proj < 2){
        __nv_bfloat16* out = (proj==0) ? g_Qb : (g_Kb + (size_t)b*SEQ*DIM);
        int mB2 = (proj==0) ? mBase : mBase;
#pragma unroll
        for (int mf=0;mf<4;mf++){
            int r0 = mB2 + wm*64 + mf*16 + gq;
#pragma unroll
            for (int j=0;j<4;j++){
                int col = nBase + wn*32 + j*8 + tig*2;
                float b0 = bias[col], b1 = bias[col+1];
                float x0 = (acc[mf][j][0]+b0)*scale, x1 = (acc[mf][j][1]+b1)*scale;
                float x2 = (acc[mf][j][2]+b0)*scale, x3 = (acc[mf][j][3]+b1)*scale;
                *(__nv_bfloat162*)&out[(size_t)r0*DIM + col]     = __floats2bfloat162_rn(x0,x1);
                *(__nv_bfloat162*)&out[(size_t)(r0+8)*DIM + col] = __floats2bfloat162_rn(x2,x3);
            }
        }
    } else {
        float* out = g_Vc + (size_t)b*SEQ*DIM;
#pragma unroll
        for (int mf=0;mf<4;mf++){
            int r0 = mBase + wm*64 + mf*16 + gq;
#pragma unroll
            for (int j=0;j<4;j++){
                int col = nBase + wn*32 + j*8 + tig*2;
                float b0 = bias[col], b1 = bias[col+1];
                *(float2*)&out[(size_t)r0*DIM + col]     = make_float2(acc[mf][j][0]+b0, acc[mf][j][1]+b1);
                *(float2*)&out[(size_t)(r0+8)*DIM + col] = make_float2(acc[mf][j][2]+b0, acc[mf][j][3]+b1);
            }
        }
    }
}

// ---------------- kernel D: scores (bf16) + exp + mask + Z partials ----------------
__global__ void __launch_bounds__(256,2) scores_k(){
    int b = blockIdx.z;
    int cnt = g_cnt[b];
    int cntp = ((cnt + 127) >> 7) << 7;
    int nBase = blockIdx.x*TN;
    if (nBase >= cntp) return;
    int mBase = blockIdx.y*TM;
    extern __shared__ __align__(16) char dsm[];
    uint32_t sb = smem_u32(dsm);
    const __nv_bfloat16** rowA = (const __nv_bfloat16**)(dsm + NSTAGE*STAGE_H);
    const __nv_bfloat16** rowB = rowA + TM;
    float* sRow = (float*)dsm;                  // reused after mainloop
    int t = threadIdx.x, L = t&31, w = t>>5;
    int wm = w&1, wn = w>>1;
    if (t < TM) rowA[t] = g_Qb + ((size_t)b*SEQ + mBase + t)*DIM;
    else        rowB[t-TM] = g_Kb + ((size_t)b*SEQ + nBase + (t-TM))*DIM;
    __syncthreads();
    uint32_t laneA = (L&15)*RSH + ((L>>4)&1)*16;
    uint32_t laneB = ((L&7) + ((L>>4)&1)*8)*RSH + ((L>>3)&1)*16;
    float acc[4][4][4] = {};
    gemm_main_h(sb, rowA, rowB, t, wm, wn, laneA, laneB, acc);

    int gq = L>>2, tig = L&3;
    __nv_bfloat16* P = g_P + (size_t)b*SEQ*SEQ;
    float zl[4] = {0,0,0,0}, zh[4] = {0,0,0,0};
#pragma unroll
    for (int mf=0;mf<4;mf++){
        int q0 = mBase + wm*64 + mf*16 + gq;
#pragma unroll
        for (int j=0;j<4;j++){
            int kcol = nBase + wn*32 + j*8 + tig*2;
            float p0 = (kcol   < cnt) ? __expf(acc[mf][j][0]) : 0.f;
            float p1 = (kcol+1 < cnt) ? __expf(acc[mf][j][1]) : 0.f;
            float p2 = (kcol   < cnt) ? __expf(acc[mf][j][2]) : 0.f;
            float p3 = (kcol+1 < cnt) ? __expf(acc[mf][j][3]) : 0.f;
            *(__nv_bfloat162*)&P[(size_t)q0*SEQ + kcol]     = __floats2bfloat162_rn(p0,p1);
            *(__nv_bfloat162*)&P[(size_t)(q0+8)*SEQ + kcol] = __floats2bfloat162_rn(p2,p3);
            zl[mf] += p0+p1; zh[mf] += p2+p3;
        }
    }
    __syncthreads();   // stage buffers no longer needed; reuse as sRow
#pragma unroll
    for (int mf=0;mf<4;mf++){
        float x0 = zl[mf];
        x0 += __shfl_xor_sync(0xffffffffu, x0, 1);
        x0 += __shfl_xor_sync(0xffffffffu, x0, 2);
        float x1 = zh[mf];
        x1 += __shfl_xor_sync(0xffffffffu, x1, 1);
        x1 += __shfl_xor_sync(0xffffffffu, x1, 2);
        if (tig==0){
            sRow[(wm*64 + mf*16 + gq)*4     + wn] = x0;
            sRow[(wm*64 + mf*16 + gq + 8)*4 + wn] = x1;
        }
    }
    __syncthreads();
    if (t < TM){
        float z = sRow[t*4] + sRow[t*4+1] + sRow[t*4+2] + sRow[t*4+3];
        g_Zpart[((size_t)b*SEQ + mBase + t)*16 + blockIdx.x] = z;
    }
}

// ---------------- kernel E: Z reduce ----------------
__global__ void zred_k(){
    int i = blockIdx.x*256 + threadIdx.x;
    if (i < MTOT){
        int b = i >> 11;
        int nt = (g_cnt[b] + 127) >> 7;
        float s = 0.f;
        for (int j=0;j<nt;j++) s += g_Zpart[(size_t)i*16 + j];
        g_invZ[i] = 1.0f/s;
    }
}

// ---------------- kernel F: cpart[b][qc][k] = sum_{q in chunk} P[q][k]*invZ[q] ----------------
__global__ void __launch_bounds__(256) colsum_k(){
    int b = blockIdx.y, qc = blockIdx.z;
    int cnt = g_cnt[b];
    int cntp = ((cnt + 127) >> 7) << 7;
    int k = blockIdx.x*256 + threadIdx.x;
    float* dst = g_cpart + ((size_t)(b*QS + qc))*SEQ;
    if (blockIdx.x*256 >= cntp){ dst[k] = 0.f; return; }
    __shared__ float sz[SEQ/QS];
    int qBase = qc*(SEQ/QS);
    for (int i=threadIdx.x; i<SEQ/QS; i+=256) sz[i] = g_invZ[b*SEQ + qBase + i];
    __syncthreads();
    const __nv_bfloat16* P = g_P + (size_t)b*SEQ*SEQ + (size_t)qBase*SEQ + k;
    float a0=0.f, a1=0.f, a2=0.f, a3=0.f;
#pragma unroll 4
    for (int q=0; q<SEQ/QS; q+=4){
        a0 += __bfloat162float(P[(size_t)(q+0)*SEQ]) * sz[q+0];
        a1 += __bfloat162float(P[(size_t)(q+1)*SEQ]) * sz[q+1];
        a2 += __bfloat162float(P[(size_t)(q+2)*SEQ]) * sz[q+2];
        a3 += __bfloat162float(P[(size_t)(q+3)*SEQ]) * sz[q+3];
    }
    dst[k] = (a0+a1)+(a2+a3);
}

// ---------------- kernel G: partial out = c @ Vc ----------------
__global__ void __launch_bounds__(256) cv_k(){
    int b  = blockIdx.y;
    int kc = blockIdx.x*64;
    int cnt = g_cnt[b];
    int cntp = ((cnt + 127) >> 7) << 7;
    float* op = g_outpart + ((size_t)b*32 + blockIdx.x)*DIM;
    int o = threadIdx.x;
    if (kc >= cntp){ op[o]=0.f; op[o+256]=0.f; op[o+512]=0.f; return; }
    __shared__ float sc[64];
    if (threadIdx.x < 64){
        float s = 0.f;
#pragma unroll
        for (int qc=0;qc<QS;qc++)
            s += g_cpart[((size_t)(b*QS + qc))*SEQ + kc + threadIdx.x];
        sc[threadIdx.x] = s;
    }
    __syncthreads();
    const float* V = g_Vc + ((size_t)b*SEQ + kc)*DIM;
    float a0=0.f, a1=0.f, a2=0.f;
    for (int k=0;k<64;k++){
        float cv = sc[k];
        const float* vr = V + (size_t)k*DIM;
        a0 += cv*vr[o]; a1 += cv*vr[o+256]; a2 += cv*vr[o+512];
    }
    op[o]=a0; op[o+256]=a1; op[o+512]=a2;
}

// ---------------- kernel H: final reduce + mean ----------------
__global__ void final_k(float* __restrict__ out){
    int b = blockIdx.x, o = threadIdx.x;
    float s = 0.f;
#pragma unroll
    for (int c=0;c<32;c++) s += g_outpart[((size_t)b*32 + c)*DIM + o];
    out[b*DIM + o] = s * (1.0f/(float)SEQ);
}

// ---------------- launch ----------------
extern "C" void kernel_launch(void* const* d_in, const int* in_sizes, int n_in,
                              void* d_out, int out_size){
    const float* x    = (const float*)d_in[0];
    const int*   mask = (const int*)  d_in[1];
    const float* Wq   = (const float*)d_in[2];
    const float* bq   = (const float*)d_in[3];
    const float* Wk   = (const float*)d_in[4];
    const float* bk   = (const float*)d_in[5];
    const float* Wv   = (const float*)d_in[6];
    const float* bv   = (const float*)d_in[7];
    float* out = (float*)d_out;

    cudaFuncSetAttribute(proj_k,   cudaFuncAttributeMaxDynamicSharedMemorySize, SMEM_DYN);
    cudaFuncSetAttribute(scores_k, cudaFuncAttributeMaxDynamicSharedMemorySize, SMEM_DYN);

    round_k <<<(MTOT*DIM/4 + 255)/256, 256>>>(x, Wq, Wk, Wv);
    prep_k  <<<NB, 256>>>(mask);
    proj_k  <<<dim3(6,384),   256, SMEM_DYN>>>(bq, bk, bv);
    scores_k<<<dim3(16,16,8), 256, SMEM_DYN>>>();
    zred_k  <<<64, 256>>>();
    colsum_k<<<dim3(8,8,QS), 256>>>();
    cv_k    <<<dim3(32,8), 256>>>();
    final_k <<<8, 768>>>(out);
}

// round 8
// speedup vs baseline: 5.5778x; 1.4741x over previous
#include <cuda_runtime.h>
#include <cuda_bf16.h>
#include <cuda_fp16.h>
#include <cstdint>

#define NB 8
#define SEQ 2048
#define DIM 768
#define MTOT (NB*SEQ)                    // 16384
#define INV_SCALE 0.03608439182435161f   // 1/sqrt(768)

// ---- unified fp16 GEMM tiling: 128x128 CTA, 4 warps (2x2), 64x64 warp tiles ----
#define TM 128
#define TN 128
#define TKH 64                           // 64 halves = 128B per stage row
#define KTH (DIM/TKH)                    // 12
#define RSH 144                          // 128B data + 16B pad
#define AH_BYTES (TM*RSH)                // 18432
#define STAGE_H (2*AH_BYTES)             // 36864
#define NSTAGE 3
#define PTR_BYTES ((TM+TN)*8)
#define SMEM_DYN (NSTAGE*STAGE_H + PTR_BYTES)   // 112640

#define QS 4                             // colsum q-split

// ---------------- static device scratch (allocation-free) ----------------
__device__ float  g_Vc[(size_t)MTOT*DIM];            // compacted V rows (fp32)
__device__ __half g_Qh[(size_t)MTOT*DIM];            // Q fp16 (scaled)
__device__ __half g_Kh[(size_t)MTOT*DIM];            // compacted K fp16
__device__ __half g_xh[(size_t)MTOT*DIM];            // x fp16
__device__ __half g_Wh[3][DIM*DIM];                  // W fp16
__device__ __nv_bfloat16 g_P[(size_t)NB*SEQ*SEQ];    // P[q][kcol]
__device__ float g_Zpart[(size_t)MTOT*16];
__device__ float g_invZ[MTOT];
__device__ float g_cpart[NB*QS*SEQ];
__device__ float g_outpart[NB*32*DIM];
__device__ int   g_idx[NB*SEQ];
__device__ int   g_cnt[NB];

// ---------------- helpers ----------------
__device__ __forceinline__ uint32_t smem_u32(const void* p){
    uint32_t a;
    asm("{ .reg .u64 t; cvta.to.shared.u64 t, %1; cvt.u32.u64 %0, t; }" : "=r"(a) : "l"(p));
    return a;
}
__device__ __forceinline__ void cp16(uint32_t d, const void* s){
    asm volatile("cp.async.cg.shared.global [%0], [%1], 16;\n" :: "r"(d), "l"(s));
}
__device__ __forceinline__ void cp_commit(){ asm volatile("cp.async.commit_group;\n" ::); }
template<int N> __device__ __forceinline__ void cp_wait(){
    asm volatile("cp.async.wait_group %0;\n" :: "n"(N));
}
__device__ __forceinline__ void ldsm4(uint32_t addr, uint32_t* r){
    asm volatile("ldmatrix.sync.aligned.m8n8.x4.shared.b16 {%0,%1,%2,%3}, [%4];\n"
        : "=r"(r[0]), "=r"(r[1]), "=r"(r[2]), "=r"(r[3]) : "r"(addr));
}
__device__ __forceinline__ void mma_f16(float* c, const uint32_t* a, uint32_t b0, uint32_t b1){
    asm volatile("mma.sync.aligned.m16n8k16.row.col.f32.f16.f16.f32 "
        "{%0,%1,%2,%3},{%4,%5,%6,%7},{%8,%9},{%0,%1,%2,%3};\n"
        : "+f"(c[0]), "+f"(c[1]), "+f"(c[2]), "+f"(c[3])
        : "r"(a[0]), "r"(a[1]), "r"(a[2]), "r"(a[3]), "r"(b0), "r"(b1));
}

// ================= fp16 GEMM core: 128x128 CTA, 4 warps, 64x64 warp tiles =================
// block = 128 threads. Per stage: A+B each 128 rows x 128B (64 halves).
__device__ __forceinline__ void issue_stage_h(uint32_t sb, int s, int k0,
        const __half* const* rowA, const __half* const* rowB, int t){
    uint32_t base = sb + s*STAGE_H;
#pragma unroll
    for (int j=0;j<8;j++){                        // A: 1024 16B chunks / 128 thr
        int ci = t + j*128; int r = ci>>3, c = ci&7;
        cp16(base + r*RSH + c*16, rowA[r] + k0 + c*8);
    }
    uint32_t bb = base + AH_BYTES;
#pragma unroll
    for (int j=0;j<8;j++){
        int ci = t + j*128; int r = ci>>3, c = ci&7;
        cp16(bb + r*RSH + c*16, rowB[r] + k0 + c*8);
    }
    cp_commit();
}

__device__ __forceinline__ void compute_stage_h(uint32_t sb, int s, int wm, int wn,
        uint32_t laneA, uint32_t laneB, float acc[4][8][4]){
    uint32_t aT = sb + s*STAGE_H + wm*64*RSH + laneA;
    uint32_t bT = sb + s*STAGE_H + AH_BYTES + wn*64*RSH + laneB;
#pragma unroll
    for (int kk=0; kk<4; kk++){                   // 4 x k16
        uint32_t a[4][4], bb[4][4];
#pragma unroll
        for (int mf=0;mf<4;mf++) ldsm4(aT + mf*16*RSH + kk*32, a[mf]);
#pragma unroll
        for (int nf=0;nf<4;nf++) ldsm4(bT + nf*16*RSH + kk*32, bb[nf]);
#pragma unroll
        for (int mf=0;mf<4;mf++)
#pragma unroll
            for (int nf=0;nf<4;nf++){
                mma_f16(acc[mf][2*nf],   a[mf], bb[nf][0], bb[nf][1]);
                mma_f16(acc[mf][2*nf+1], a[mf], bb[nf][2], bb[nf][3]);
            }
    }
}

__device__ __forceinline__ void gemm_main_h(uint32_t sb, const __half* const* rowA,
        const __half* const* rowB, int t, int wm, int wn,
        uint32_t laneA, uint32_t laneB, float acc[4][8][4]){
    issue_stage_h(sb, 0, 0,   rowA, rowB, t);
    issue_stage_h(sb, 1, TKH, rowA, rowB, t);
#pragma unroll 1
    for (int it=0; it<KTH; ++it){
        if (it < KTH-1) cp_wait<1>(); else cp_wait<0>();
        __syncthreads();
        if (it+2 < KTH) issue_stage_h(sb, (it+2)%NSTAGE, (it+2)*TKH, rowA, rowB, t);
        compute_stage_h(sb, it%NSTAGE, wm, wn, laneA, laneB, acc);
    }
}

// ---------------- kernel A: fp16 conversion ----------------
__global__ void round_k(const float* __restrict__ x, const float* __restrict__ Wq,
                        const float* __restrict__ Wk, const float* __restrict__ Wv){
    size_t i = ((size_t)blockIdx.x*256 + threadIdx.x)*4;
    if (i < (size_t)MTOT*DIM){
        float4 v = *(const float4*)(x+i);
        __half2 h0 = __floats2half2_rn(v.x, v.y), h1 = __floats2half2_rn(v.z, v.w);
        *(__half2*)(g_xh+i) = h0; *(__half2*)(g_xh+i+2) = h1;
    }
    if (i < (size_t)DIM*DIM){
        float4 q = *(const float4*)(Wq+i);
        *(__half2*)(&g_Wh[0][i])   = __floats2half2_rn(q.x,q.y);
        *(__half2*)(&g_Wh[0][i+2]) = __floats2half2_rn(q.z,q.w);
        float4 k = *(const float4*)(Wk+i);
        *(__half2*)(&g_Wh[1][i])   = __floats2half2_rn(k.x,k.y);
        *(__half2*)(&g_Wh[1][i+2]) = __floats2half2_rn(k.z,k.w);
        float4 w = *(const float4*)(Wv+i);
        *(__half2*)(&g_Wh[2][i])   = __floats2half2_rn(w.x,w.y);
        *(__half2*)(&g_Wh[2][i+2]) = __floats2half2_rn(w.z,w.w);
    }
}

// ---------------- kernel B: mask prefix-scan -> compact index list ----------------
__global__ void prep_k(const int* __restrict__ mask){
    int b = blockIdx.x, t = threadIdx.x;
    __shared__ int sm[SEQ];
    __shared__ int ws[8];
    for (int i=t;i<SEQ;i+=256) sm[i] = mask[b*SEQ+i];
    __syncthreads();
    int base_i = t*8;
    int loc[8], s=0;
#pragma unroll
    for (int j=0;j<8;j++){ loc[j]=s; s += sm[base_i+j]; }
    int lane = t&31, w = t>>5;
    int v = s;
#pragma unroll
    for (int off=1; off<32; off<<=1){
        int n = __shfl_up_sync(0xffffffffu, v, off);
        if (lane >= off) v += n;
    }
    if (lane==31) ws[w] = v;
    __syncthreads();
    int wbase = 0;
#pragma unroll
    for (int i=0;i<8;i++) if (i<w) wbase += ws[i];
    int excl = wbase + v - s;
#pragma unroll
    for (int j=0;j<8;j++)
        if (sm[base_i+j]) g_idx[b*SEQ + excl + loc[j]] = base_i+j;
    if (t==255) g_cnt[b] = wbase + v;
}

// ---------------- kernel C: fused Q/K/V projections (fp16 mma) ----------------
// grid = (6, 384): y<128 -> Q; 128..255 -> K; 256..383 -> V. block = 128.
__global__ void __launch_bounds__(128,2) proj_k(const float* __restrict__ bq,
        const float* __restrict__ bk, const float* __restrict__ bv){
    extern __shared__ __align__(16) char dsm[];
    uint32_t sb = smem_u32(dsm);
    const __half** rowA = (const __half**)(dsm + NSTAGE*STAGE_H);
    const __half** rowB = rowA + TM;
    int t = threadIdx.x, L = t&31, w = t>>5;
    int wm = w&1, wn = w>>1;
    int y = blockIdx.y;
    int proj = (y < 128) ? 0 : ((y < 256) ? 1 : 2);
    int nBase = blockIdx.x*TN;

    int mBase, b = 0;
    if (proj == 0){
        mBase = y*TM;
    } else {
        int i = y - (proj==1 ? 128 : 256);
        b = i >> 4;
        mBase = (i & 15)*TM;
        int cnt = g_cnt[b];
        int cntp = ((cnt + 127) >> 7) << 7;
        if (mBase >= cntp) return;
    }
    if (proj == 0){
        rowA[t] = g_xh + (size_t)(mBase + t)*DIM;
    } else {
        int cnt = g_cnt[b];
        int j = mBase + t; if (j >= cnt) j = cnt-1;
        rowA[t] = g_xh + ((size_t)b*SEQ + g_idx[b*SEQ + j])*DIM;
    }
    rowB[t] = g_Wh[proj] + (size_t)(nBase + t)*DIM;
    __syncthreads();

    uint32_t laneA = (L&15)*RSH + ((L>>4)&1)*16;
    uint32_t laneB = ((L&7) + ((L>>4)&1)*8)*RSH + ((L>>3)&1)*16;
    float acc[4][8][4] = {};
    gemm_main_h(sb, rowA, rowB, t, wm, wn, laneA, laneB, acc);

    const float* bias = proj==0 ? bq : (proj==1 ? bk : bv);
    float scale = proj==0 ? INV_SCALE : 1.0f;
    int gq = L>>2, tig = L&3;
    if (proj < 2){
        __half* out = (proj==0) ? g_Qh : (g_Kh + (size_t)b*SEQ*DIM);
#pragma unroll
        for (int mf=0;mf<4;mf++){
            int r0 = mBase + wm*64 + mf*16 + gq;
#pragma unroll
            for (int j=0;j<8;j++){
                int col = nBase + wn*64 + (j>>1)*16 + (j&1)*8 + tig*2;
                float b0 = bias[col], b1 = bias[col+1];
                float x0 = (acc[mf][j][0]+b0)*scale, x1 = (acc[mf][j][1]+b1)*scale;
                float x2 = (acc[mf][j][2]+b0)*scale, x3 = (acc[mf][j][3]+b1)*scale;
                *(__half2*)&out[(size_t)r0*DIM + col]     = __floats2half2_rn(x0,x1);
                *(__half2*)&out[(size_t)(r0+8)*DIM + col] = __floats2half2_rn(x2,x3);
            }
        }
    } else {
        float* out = g_Vc + (size_t)b*SEQ*DIM;
#pragma unroll
        for (int mf=0;mf<4;mf++){
            int r0 = mBase + wm*64 + mf*16 + gq;
#pragma unroll
            for (int j=0;j<8;j++){
                int col = nBase + wn*64 + (j>>1)*16 + (j&1)*8 + tig*2;
                float b0 = bias[col], b1 = bias[col+1];
                *(float2*)&out[(size_t)r0*DIM + col]     = make_float2(acc[mf][j][0]+b0, acc[mf][j][1]+b1);
                *(float2*)&out[(size_t)(r0+8)*DIM + col] = make_float2(acc[mf][j][2]+b0, acc[mf][j][3]+b1);
            }
        }
    }
}

// ---------------- kernel D: scores (fp16) + exp + mask + Z partials ----------------
__global__ void __launch_bounds__(128,2) scores_k(){
    int b = blockIdx.z;
    int cnt = g_cnt[b];
    int cntp = ((cnt + 127) >> 7) << 7;
    int nBase = blockIdx.x*TN;
    if (nBase >= cntp) return;
    int mBase = blockIdx.y*TM;
    extern __shared__ __align__(16) char dsm[];
    uint32_t sb = smem_u32(dsm);
    const __half** rowA = (const __half**)(dsm + NSTAGE*STAGE_H);
    const __half** rowB = rowA + TM;
    float* sRow = (float*)dsm;                  // reused after mainloop
    int t = threadIdx.x, L = t&31, w = t>>5;
    int wm = w&1, wn = w>>1;
    rowA[t] = g_Qh + ((size_t)b*SEQ + mBase + t)*DIM;
    rowB[t] = g_Kh + ((size_t)b*SEQ + nBase + t)*DIM;
    __syncthreads();
    uint32_t laneA = (L&15)*RSH + ((L>>4)&1)*16;
    uint32_t laneB = ((L&7) + ((L>>4)&1)*8)*RSH + ((L>>3)&1)*16;
    float acc[4][8][4] = {};
    gemm_main_h(sb, rowA, rowB, t, wm, wn, laneA, laneB, acc);

    int gq = L>>2, tig = L&3;
    __nv_bfloat16* P = g_P + (size_t)b*SEQ*SEQ;
    float zl[4] = {0,0,0,0}, zh[4] = {0,0,0,0};
#pragma unroll
    for (int mf=0;mf<4;mf++){
        int q0 = mBase + wm*64 + mf*16 + gq;
#pragma unroll
        for (int j=0;j<8;j++){
            int kcol = nBase + wn*64 + (j>>1)*16 + (j&1)*8 + tig*2;
            float p0 = (kcol   < cnt) ? __expf(acc[mf][j][0]) : 0.f;
            float p1 = (kcol+1 < cnt) ? __expf(acc[mf][j][1]) : 0.f;
            float p2 = (kcol   < cnt) ? __expf(acc[mf][j][2]) : 0.f;
            float p3 = (kcol+1 < cnt) ? __expf(acc[mf][j][3]) : 0.f;
            *(__nv_bfloat162*)&P[(size_t)q0*SEQ + kcol]     = __floats2bfloat162_rn(p0,p1);
            *(__nv_bfloat162*)&P[(size_t)(q0+8)*SEQ + kcol] = __floats2bfloat162_rn(p2,p3);
            zl[mf] += p0+p1; zh[mf] += p2+p3;
        }
    }
    __syncthreads();   // stage buffers done; reuse as sRow
#pragma unroll
    for (int mf=0;mf<4;mf++){
        float x0 = zl[mf];
        x0 += __shfl_xor_sync(0xffffffffu, x0, 1);
        x0 += __shfl_xor_sync(0xffffffffu, x0, 2);
        float x1 = zh[mf];
        x1 += __shfl_xor_sync(0xffffffffu, x1, 1);
        x1 += __shfl_xor_sync(0xffffffffu, x1, 2);
        if (tig==0){
            sRow[(wm*64 + mf*16 + gq)*2     + wn] = x0;
            sRow[(wm*64 + mf*16 + gq + 8)*2 + wn] = x1;
        }
    }
    __syncthreads();
    if (t < TM){
        float z = sRow[t*2] + sRow[t*2+1];
        g_Zpart[((size_t)b*SEQ + mBase + t)*16 + blockIdx.x] = z;
    }
}

// ---------------- kernel E: Z reduce ----------------
__global__ void zred_k(){
    int i = blockIdx.x*256 + threadIdx.x;
    if (i < MTOT){
        int b = i >> 11;
        int nt = (g_cnt[b] + 127) >> 7;
        float s = 0.f;
        for (int j=0;j<nt;j++) s += g_Zpart[(size_t)i*16 + j];
        g_invZ[i] = 1.0f/s;
    }
}

// ---------------- kernel F: cpart[b][qc][k] = sum_{q in chunk} P[q][k]*invZ[q] --------
__global__ void __launch_bounds__(256) colsum_k(){
    int b = blockIdx.y, qc = blockIdx.z;
    int cnt = g_cnt[b];
    int cntp = ((cnt + 127) >> 7) << 7;
    int k = blockIdx.x*256 + threadIdx.x;
    float* dst = g_cpart + ((size_t)(b*QS + qc))*SEQ;
    if (blockIdx.x*256 >= cntp){ dst[k] = 0.f; return; }
    __shared__ float sz[SEQ/QS];
    int qBase = qc*(SEQ/QS);
    for (int i=threadIdx.x; i<SEQ/QS; i+=256) sz[i] = g_invZ[b*SEQ + qBase + i];
    __syncthreads();
    const __nv_bfloat16* P = g_P + (size_t)b*SEQ*SEQ + (size_t)qBase*SEQ + k;
    float a0=0.f, a1=0.f, a2=0.f, a3=0.f;
#pragma unroll 4
    for (int q=0; q<SEQ/QS; q+=4){
        a0 += __bfloat162float(P[(size_t)(q+0)*SEQ]) * sz[q+0];
        a1 += __bfloat162float(P[(size_t)(q+1)*SEQ]) * sz[q+1];
        a2 += __bfloat162float(P[(size_t)(q+2)*SEQ]) * sz[q+2];
        a3 += __bfloat162float(P[(size_t)(q+3)*SEQ]) * sz[q+3];
    }
    dst[k] = (a0+a1)+(a2+a3);
}

// ---------------- kernel G: partial out = c @ Vc ----------------
__global__ void __launch_bounds__(256) cv_k(){
    int b  = blockIdx.y;
    int kc = blockIdx.x*64;
    int cnt = g_cnt[b];
    int cntp = ((cnt + 127) >> 7) << 7;
    float* op = g_outpart + ((size_t)b*32 + blockIdx.x)*DIM;
    int o = threadIdx.x;
    if (kc >= cntp){ op[o]=0.f; op[o+256]=0.f; op[o+512]=0.f; return; }
    __shared__ float sc[64];
    if (threadIdx.x < 64){
        float s = 0.f;
#pragma unroll
        for (int qc=0;qc<QS;qc++)
            s += g_cpart[((size_t)(b*QS + qc))*SEQ + kc + threadIdx.x];
        sc[threadIdx.x] = s;
    }
    __syncthreads();
    const float* V = g_Vc + ((size_t)b*SEQ + kc)*DIM;
    float a0=0.f, a1=0.f, a2=0.f;
    for (int k=0;k<64;k++){
        float cv = sc[k];
        const float* vr = V + (size_t)k*DIM;
        a0 += cv*vr[o]; a1 += cv*vr[o+256]; a2 += cv*vr[o+512];
    }
    op[o]=a0; op[o+256]=a1; op[o+512]=a2;
}

// ---------------- kernel H: final reduce + mean ----------------
__global__ void final_k(float* __restrict__ out){
    int b = blockIdx.x, o = threadIdx.x;
    float s = 0.f;
#pragma unroll
    for (int c=0;c<32;c++) s += g_outpart[((size_t)b*32 + c)*DIM + o];
    out[b*DIM + o] = s * (1.0f/(float)SEQ);
}

// ---------------- launch ----------------
extern "C" void kernel_launch(void* const* d_in, const int* in_sizes, int n_in,
                              void* d_out, int out_size){
    const float* x    = (const float*)d_in[0];
    const int*   mask = (const int*)  d_in[1];
    const float* Wq   = (const float*)d_in[2];
    const float* bq   = (const float*)d_in[3];
    const float* Wk   = (const float*)d_in[4];
    const float* bk   = (const float*)d_in[5];
    const float* Wv   = (const float*)d_in[6];
    const float* bv   = (const float*)d_in[7];
    float* out = (float*)d_out;

    cudaFuncSetAttribute(proj_k,   cudaFuncAttributeMaxDynamicSharedMemorySize, SMEM_DYN);
    cudaFuncSetAttribute(scores_k, cudaFuncAttributeMaxDynamicSharedMemorySize, SMEM_DYN);

    round_k <<<(MTOT*DIM/4 + 255)/256, 256>>>(x, Wq, Wk, Wv);
    prep_k  <<<NB, 256>>>(mask);
    proj_k  <<<dim3(6,384),   128, SMEM_DYN>>>(bq, bk, bv);
    scores_k<<<dim3(16,16,8), 128, SMEM_DYN>>>();
    zred_k  <<<64, 256>>>();
    colsum_k<<<dim3(8,8,QS), 256>>>();
    cv_k    <<<dim3(32,8), 256>>>();
    final_k <<<8, 768>>>(out);
}

// round 9
// speedup vs baseline: 5.8860x; 1.0552x over previous
#include <cuda_runtime.h>
#include <cuda_bf16.h>
#include <cuda_fp16.h>
#include <cstdint>

#define NB 8
#define SEQ 2048
#define DIM 768
#define MTOT (NB*SEQ)                    // 16384
#define INV_SCALE 0.03608439182435161f   // 1/sqrt(768)

// ---- unified fp16 GEMM tiling: 128x128 CTA, 4 warps (2x2), 64x64 warp tiles ----
#define TM 128
#define TN 128
#define TKH 64                           // 64 halves = 128B per stage row
#define KTH (DIM/TKH)                    // 12
#define RSH 144                          // 128B data + 16B pad
#define AH_BYTES (TM*RSH)                // 18432
#define STAGE_H (2*AH_BYTES)             // 36864
#define NSTAGE 3
#define PTR_BYTES ((TM+TN)*8)
#define SMEM_DYN (NSTAGE*STAGE_H + PTR_BYTES)   // 112640

#define QS 8                             // colsum q-split

// ---------------- static device scratch (allocation-free) ----------------
__device__ float  g_Vc[(size_t)MTOT*DIM];            // compacted V rows (fp32)
__device__ __half g_Qh[(size_t)MTOT*DIM];            // Q fp16 (scaled)
__device__ __half g_Kh[(size_t)MTOT*DIM];            // compacted K fp16
__device__ __half g_xh[(size_t)MTOT*DIM];            // x fp16
__device__ __half g_Wh[3][DIM*DIM];                  // W fp16
__device__ __nv_bfloat16 g_P[(size_t)NB*SEQ*SEQ];    // P[q][kcol]
__device__ float g_Zpart[(size_t)MTOT*16];
__device__ float g_invZ[MTOT];
__device__ float g_cpart[NB*QS*SEQ];
__device__ float g_outpart[NB*32*DIM];
__device__ int   g_idx[NB*SEQ];
__device__ int   g_cnt[NB];

// ---------------- helpers ----------------
__device__ __forceinline__ uint32_t smem_u32(const void* p){
    uint32_t a;
    asm("{ .reg .u64 t; cvta.to.shared.u64 t, %1; cvt.u32.u64 %0, t; }" : "=r"(a) : "l"(p));
    return a;
}
__device__ __forceinline__ void cp16(uint32_t d, const void* s){
    asm volatile("cp.async.cg.shared.global [%0], [%1], 16;\n" :: "r"(d), "l"(s));
}
__device__ __forceinline__ void cp_commit(){ asm volatile("cp.async.commit_group;\n" ::); }
template<int N> __device__ __forceinline__ void cp_wait(){
    asm volatile("cp.async.wait_group %0;\n" :: "n"(N));
}
__device__ __forceinline__ void ldsm4(uint32_t addr, uint32_t* r){
    asm volatile("ldmatrix.sync.aligned.m8n8.x4.shared.b16 {%0,%1,%2,%3}, [%4];\n"
        : "=r"(r[0]), "=r"(r[1]), "=r"(r[2]), "=r"(r[3]) : "r"(addr));
}
__device__ __forceinline__ void mma_f16(float* c, const uint32_t* a, uint32_t b0, uint32_t b1){
    asm volatile("mma.sync.aligned.m16n8k16.row.col.f32.f16.f16.f32 "
        "{%0,%1,%2,%3},{%4,%5,%6,%7},{%8,%9},{%0,%1,%2,%3};\n"
        : "+f"(c[0]), "+f"(c[1]), "+f"(c[2]), "+f"(c[3])
        : "r"(a[0]), "r"(a[1]), "r"(a[2]), "r"(a[3]), "r"(b0), "r"(b1));
}

// ================= fp16 GEMM core: 128x128 CTA, 4 warps, 64x64 warp tiles =================
__device__ __forceinline__ void issue_stage_h(uint32_t sb, int s, int k0,
        const __half* const* rowA, const __half* const* rowB, int t){
    uint32_t base = sb + s*STAGE_H;
#pragma unroll
    for (int j=0;j<8;j++){                        // A: 1024 16B chunks / 128 thr
        int ci = t + j*128; int r = ci>>3, c = ci&7;
        cp16(base + r*RSH + c*16, rowA[r] + k0 + c*8);
    }
    uint32_t bb = base + AH_BYTES;
#pragma unroll
    for (int j=0;j<8;j++){
        int ci = t + j*128; int r = ci>>3, c = ci&7;
        cp16(bb + r*RSH + c*16, rowB[r] + k0 + c*8);
    }
    cp_commit();
}

// kk-loop software-pipelined: ldsm for kk+1 issued before MMAs of kk.
__device__ __forceinline__ void compute_stage_h(uint32_t sb, int s, int wm, int wn,
        uint32_t laneA, uint32_t laneB, float acc[4][8][4]){
    uint32_t aT = sb + s*STAGE_H + wm*64*RSH + laneA;
    uint32_t bT = sb + s*STAGE_H + AH_BYTES + wn*64*RSH + laneB;
    uint32_t a[2][4][4], bb[2][4][4];
#pragma unroll
    for (int mf=0;mf<4;mf++) ldsm4(aT + mf*16*RSH, a[0][mf]);
#pragma unroll
    for (int nf=0;nf<4;nf++) ldsm4(bT + nf*16*RSH, bb[0][nf]);
#pragma unroll
    for (int kk=0; kk<4; kk++){
        int cur = kk&1, nxt = cur^1;
        if (kk < 3){
#pragma unroll
            for (int mf=0;mf<4;mf++) ldsm4(aT + mf*16*RSH + (kk+1)*32, a[nxt][mf]);
#pragma unroll
            for (int nf=0;nf<4;nf++) ldsm4(bT + nf*16*RSH + (kk+1)*32, bb[nxt][nf]);
        }
#pragma unroll
        for (int mf=0;mf<4;mf++)
#pragma unroll
            for (int nf=0;nf<4;nf++){
                mma_f16(acc[mf][2*nf],   a[cur][mf], bb[cur][nf][0], bb[cur][nf][1]);
                mma_f16(acc[mf][2*nf+1], a[cur][mf], bb[cur][nf][2], bb[cur][nf][3]);
            }
    }
}

__device__ __forceinline__ void gemm_main_h(uint32_t sb, const __half* const* rowA,
        const __half* const* rowB, int t, int wm, int wn,
        uint32_t laneA, uint32_t laneB, float acc[4][8][4]){
    issue_stage_h(sb, 0, 0,   rowA, rowB, t);
    issue_stage_h(sb, 1, TKH, rowA, rowB, t);
#pragma unroll 1
    for (int it=0; it<KTH; ++it){
        if (it < KTH-1) cp_wait<1>(); else cp_wait<0>();
        __syncthreads();
        if (it+2 < KTH) issue_stage_h(sb, (it+2)%NSTAGE, (it+2)*TKH, rowA, rowB, t);
        compute_stage_h(sb, it%NSTAGE, wm, wn, laneA, laneB, acc);
    }
}

// ---------------- kernel A: fp16 conversion ----------------
__global__ void round_k(const float* __restrict__ x, const float* __restrict__ Wq,
                        const float* __restrict__ Wk, const float* __restrict__ Wv){
    size_t i = ((size_t)blockIdx.x*256 + threadIdx.x)*4;
    if (i < (size_t)MTOT*DIM){
        float4 v = *(const float4*)(x+i);
        __half2 h0 = __floats2half2_rn(v.x, v.y), h1 = __floats2half2_rn(v.z, v.w);
        *(__half2*)(g_xh+i) = h0; *(__half2*)(g_xh+i+2) = h1;
    }
    if (i < (size_t)DIM*DIM){
        float4 q = *(const float4*)(Wq+i);
        *(__half2*)(&g_Wh[0][i])   = __floats2half2_rn(q.x,q.y);
        *(__half2*)(&g_Wh[0][i+2]) = __floats2half2_rn(q.z,q.w);
        float4 k = *(const float4*)(Wk+i);
        *(__half2*)(&g_Wh[1][i])   = __floats2half2_rn(k.x,k.y);
        *(__half2*)(&g_Wh[1][i+2]) = __floats2half2_rn(k.z,k.w);
        float4 w = *(const float4*)(Wv+i);
        *(__half2*)(&g_Wh[2][i])   = __floats2half2_rn(w.x,w.y);
        *(__half2*)(&g_Wh[2][i+2]) = __floats2half2_rn(w.z,w.w);
    }
}

// ---------------- kernel B: mask prefix-scan -> compact index list ----------------
__global__ void prep_k(const int* __restrict__ mask){
    int b = blockIdx.x, t = threadIdx.x;
    __shared__ int sm[SEQ];
    __shared__ int ws[8];
    for (int i=t;i<SEQ;i+=256) sm[i] = mask[b*SEQ+i];
    __syncthreads();
    int base_i = t*8;
    int loc[8], s=0;
#pragma unroll
    for (int j=0;j<8;j++){ loc[j]=s; s += sm[base_i+j]; }
    int lane = t&31, w = t>>5;
    int v = s;
#pragma unroll
    for (int off=1; off<32; off<<=1){
        int n = __shfl_up_sync(0xffffffffu, v, off);
        if (lane >= off) v += n;
    }
    if (lane==31) ws[w] = v;
    __syncthreads();
    int wbase = 0;
#pragma unroll
    for (int i=0;i<8;i++) if (i<w) wbase += ws[i];
    int excl = wbase + v - s;
#pragma unroll
    for (int j=0;j<8;j++)
        if (sm[base_i+j]) g_idx[b*SEQ + excl + loc[j]] = base_i+j;
    if (t==255) g_cnt[b] = wbase + v;
}

// ---------------- kernel C: fused Q/K/V projections (fp16 mma) ----------------
// grid = (6, 384): y<128 -> Q; 128..255 -> K; 256..383 -> V. block = 128.
__global__ void __launch_bounds__(128,2) proj_k(const float* __restrict__ bq,
        const float* __restrict__ bk, const float* __restrict__ bv){
    extern __shared__ __align__(16) char dsm[];
    uint32_t sb = smem_u32(dsm);
    const __half** rowA = (const __half**)(dsm + NSTAGE*STAGE_H);
    const __half** rowB = rowA + TM;
    int t = threadIdx.x, L = t&31, w = t>>5;
    int wm = w&1, wn = w>>1;
    int y = blockIdx.y;
    int proj = (y < 128) ? 0 : ((y < 256) ? 1 : 2);
    int nBase = blockIdx.x*TN;

    int mBase, b = 0;
    if (proj == 0){
        mBase = y*TM;
    } else {
        int i = y - (proj==1 ? 128 : 256);
        b = i >> 4;
        mBase = (i & 15)*TM;
        int cnt = g_cnt[b];
        int cntp = ((cnt + 127) >> 7) << 7;
        if (mBase >= cntp) return;
    }
    if (proj == 0){
        rowA[t] = g_xh + (size_t)(mBase + t)*DIM;
    } else {
        int cnt = g_cnt[b];
        int j = mBase + t; if (j >= cnt) j = cnt-1;
        rowA[t] = g_xh + ((size_t)b*SEQ + g_idx[b*SEQ + j])*DIM;
    }
    rowB[t] = g_Wh[proj] + (size_t)(nBase + t)*DIM;
    __syncthreads();

    uint32_t laneA = (L&15)*RSH + ((L>>4)&1)*16;
    uint32_t laneB = ((L&7) + ((L>>4)&1)*8)*RSH + ((L>>3)&1)*16;
    float acc[4][8][4] = {};
    gemm_main_h(sb, rowA, rowB, t, wm, wn, laneA, laneB, acc);

    const float* bias = proj==0 ? bq : (proj==1 ? bk : bv);
    float scale = proj==0 ? INV_SCALE : 1.0f;
    int gq = L>>2, tig = L&3;
    if (proj < 2){
        __half* out = (proj==0) ? g_Qh : (g_Kh + (size_t)b*SEQ*DIM);
#pragma unroll
        for (int mf=0;mf<4;mf++){
            int r0 = mBase + wm*64 + mf*16 + gq;
#pragma unroll
            for (int j=0;j<8;j++){
                int col = nBase + wn*64 + (j>>1)*16 + (j&1)*8 + tig*2;
                float b0 = bias[col], b1 = bias[col+1];
                float x0 = (acc[mf][j][0]+b0)*scale, x1 = (acc[mf][j][1]+b1)*scale;
                float x2 = (acc[mf][j][2]+b0)*scale, x3 = (acc[mf][j][3]+b1)*scale;
                *(__half2*)&out[(size_t)r0*DIM + col]     = __floats2half2_rn(x0,x1);
                *(__half2*)&out[(size_t)(r0+8)*DIM + col] = __floats2half2_rn(x2,x3);
            }
        }
    } else {
        float* out = g_Vc + (size_t)b*SEQ*DIM;
#pragma unroll
        for (int mf=0;mf<4;mf++){
            int r0 = mBase + wm*64 + mf*16 + gq;
#pragma unroll
            for (int j=0;j<8;j++){
                int col = nBase + wn*64 + (j>>1)*16 + (j&1)*8 + tig*2;
                float b0 = bias[col], b1 = bias[col+1];
                *(float2*)&out[(size_t)r0*DIM + col]     = make_float2(acc[mf][j][0]+b0, acc[mf][j][1]+b1);
                *(float2*)&out[(size_t)(r0+8)*DIM + col] = make_float2(acc[mf][j][2]+b0, acc[mf][j][3]+b1);
            }
        }
    }
}

// ---------------- kernel D: scores (fp16) + exp + mask + Z partials ----------------
__global__ void __launch_bounds__(128,2) scores_k(){
    int b = blockIdx.z;
    int cnt = g_cnt[b];
    int cntp = ((cnt + 127) >> 7) << 7;
    int nBase = blockIdx.x*TN;
    if (nBase >= cntp) return;
    int mBase = blockIdx.y*TM;
    extern __shared__ __align__(16) char dsm[];
    uint32_t sb = smem_u32(dsm);
    const __half** rowA = (const __half**)(dsm + NSTAGE*STAGE_H);
    const __half** rowB = rowA + TM;
    float* sRow = (float*)dsm;                  // reused after mainloop
    int t = threadIdx.x, L = t&31, w = t>>5;
    int wm = w&1, wn = w>>1;
    rowA[t] = g_Qh + ((size_t)b*SEQ + mBase + t)*DIM;
    rowB[t] = g_Kh + ((size_t)b*SEQ + nBase + t)*DIM;
    __syncthreads();
    uint32_t laneA = (L&15)*RSH + ((L>>4)&1)*16;
    uint32_t laneB = ((L&7) + ((L>>4)&1)*8)*RSH + ((L>>3)&1)*16;
    float acc[4][8][4] = {};
    gemm_main_h(sb, rowA, rowB, t, wm, wn, laneA, laneB, acc);

    int gq = L>>2, tig = L&3;
    __nv_bfloat16* P = g_P + (size_t)b*SEQ*SEQ;
    float zl[4] = {0,0,0,0}, zh[4] = {0,0,0,0};
#pragma unroll
    for (int mf=0;mf<4;mf++){
        int q0 = mBase + wm*64 + mf*16 + gq;
#pragma unroll
        for (int j=0;j<8;j++){
            int kcol = nBase + wn*64 + (j>>1)*16 + (j&1)*8 + tig*2;
            float p0 = (kcol   < cnt) ? __expf(acc[mf][j][0]) : 0.f;
            float p1 = (kcol+1 < cnt) ? __expf(acc[mf][j][1]) : 0.f;
            float p2 = (kcol   < cnt) ? __expf(acc[mf][j][2]) : 0.f;
            float p3 = (kcol+1 < cnt) ? __expf(acc[mf][j][3]) : 0.f;
            *(__nv_bfloat162*)&P[(size_t)q0*SEQ + kcol]     = __floats2bfloat162_rn(p0,p1);
            *(__nv_bfloat162*)&P[(size_t)(q0+8)*SEQ + kcol] = __floats2bfloat162_rn(p2,p3);
            zl[mf] += p0+p1; zh[mf] += p2+p3;
        }
    }
    __syncthreads();   // stage buffers done; reuse as sRow
#pragma unroll
    for (int mf=0;mf<4;mf++){
        float x0 = zl[mf];
        x0 += __shfl_xor_sync(0xffffffffu, x0, 1);
        x0 += __shfl_xor_sync(0xffffffffu, x0, 2);
        float x1 = zh[mf];
        x1 += __shfl_xor_sync(0xffffffffu, x1, 1);
        x1 += __shfl_xor_sync(0xffffffffu, x1, 2);
        if (tig==0){
            sRow[(wm*64 + mf*16 + gq)*2     + wn] = x0;
            sRow[(wm*64 + mf*16 + gq + 8)*2 + wn] = x1;
        }
    }
    __syncthreads();
    if (t < TM){
        float z = sRow[t*2] + sRow[t*2+1];
        g_Zpart[((size_t)b*SEQ + mBase + t)*16 + blockIdx.x] = z;
    }
}

// ---------------- kernel E: Z reduce ----------------
__global__ void zred_k(){
    int i = blockIdx.x*256 + threadIdx.x;
    if (i < MTOT){
        int b = i >> 11;
        int nt = (g_cnt[b] + 127) >> 7;
        float s = 0.f;
        for (int j=0;j<nt;j++) s += g_Zpart[(size_t)i*16 + j];
        g_invZ[i] = 1.0f/s;
    }
}

// ---------------- kernel F: cpart[b][qc][k] = sum_{q in chunk} P[q][k]*invZ[q] --------
__global__ void __launch_bounds__(256) colsum_k(){
    int b = blockIdx.y, qc = blockIdx.z;
    int cnt = g_cnt[b];
    int cntp = ((cnt + 127) >> 7) << 7;
    int k = blockIdx.x*256 + threadIdx.x;
    float* dst = g_cpart + ((size_t)(b*QS + qc))*SEQ;
    if (blockIdx.x*256 >= cntp){ dst[k] = 0.f; return; }
    __shared__ float sz[SEQ/QS];
    int qBase = qc*(SEQ/QS);
    for (int i=threadIdx.x; i<SEQ/QS; i+=256) sz[i] = g_invZ[b*SEQ + qBase + i];
    __syncthreads();
    const __nv_bfloat16* P = g_P + (size_t)b*SEQ*SEQ + (size_t)qBase*SEQ + k;
    float a0=0.f, a1=0.f, a2=0.f, a3=0.f;
#pragma unroll 4
    for (int q=0; q<SEQ/QS; q+=4){
        a0 += __bfloat162float(P[(size_t)(q+0)*SEQ]) * sz[q+0];
        a1 += __bfloat162float(P[(size_t)(q+1)*SEQ]) * sz[q+1];
        a2 += __bfloat162float(P[(size_t)(q+2)*SEQ]) * sz[q+2];
        a3 += __bfloat162float(P[(size_t)(q+3)*SEQ]) * sz[q+3];
    }
    dst[k] = (a0+a1)+(a2+a3);
}

// ---------------- kernel G: partial out = c @ Vc ----------------
__global__ void __launch_bounds__(256) cv_k(){
    int b  = blockIdx.y;
    int kc = blockIdx.x*64;
    int cnt = g_cnt[b];
    int cntp = ((cnt + 127) >> 7) << 7;
    float* op = g_outpart + ((size_t)b*32 + blockIdx.x)*DIM;
    int o = threadIdx.x;
    if (kc >= cntp){ op[o]=0.f; op[o+256]=0.f; op[o+512]=0.f; return; }
    __shared__ float sc[64];
    if (threadIdx.x < 64){
        float s = 0.f;
#pragma unroll
        for (int qc=0;qc<QS;qc++)
            s += g_cpart[((size_t)(b*QS + qc))*SEQ + kc + threadIdx.x];
        sc[threadIdx.x] = s;
    }
    __syncthreads();
    const float* V = g_Vc + ((size_t)b*SEQ + kc)*DIM;
    float a0=0.f, a1=0.f, a2=0.f;
    for (int k=0;k<64;k++){
        float cv = sc[k];
        const float* vr = V + (size_t)k*DIM;
        a0 += cv*vr[o]; a1 += cv*vr[o+256]; a2 += cv*vr[o+512];
    }
    op[o]=a0; op[o+256]=a1; op[o+512]=a2;
}

// ---------------- kernel H: final reduce + mean ----------------
__global__ void final_k(float* __restrict__ out){
    int b = blockIdx.x, o = threadIdx.x;
    float s = 0.f;
#pragma unroll
    for (int c=0;c<32;c++) s += g_outpart[((size_t)b*32 + c)*DIM + o];
    out[b*DIM + o] = s * (1.0f/(float)SEQ);
}

// ---------------- launch ----------------
extern "C" void kernel_launch(void* const* d_in, const int* in_sizes, int n_in,
                              void* d_out, int out_size){
    const float* x    = (const float*)d_in[0];
    const int*   mask = (const int*)  d_in[1];
    const float* Wq   = (const float*)d_in[2];
    const float* bq   = (const float*)d_in[3];
    const float* Wk   = (const float*)d_in[4];
    const float* bk   = (const float*)d_in[5];
    const float* Wv   = (const float*)d_in[6];
    const float* bv   = (const float*)d_in[7];
    float* out = (float*)d_out;

    cudaFuncSetAttribute(proj_k,   cudaFuncAttributeMaxDynamicSharedMemorySize, SMEM_DYN);
    cudaFuncSetAttribute(scores_k, cudaFuncAttributeMaxDynamicSharedMemorySize, SMEM_DYN);

    round_k <<<(MTOT*DIM/4 + 255)/256, 256>>>(x, Wq, Wk, Wv);
    prep_k  <<<NB, 256>>>(mask);
    proj_k  <<<dim3(6,384),   128, SMEM_DYN>>>(bq, bk, bv);
    scores_k<<<dim3(16,16,8), 128, SMEM_DYN>>>();
    zred_k  <<<64, 256>>>();
    colsum_k<<<dim3(8,8,QS), 256>>>();
    cv_k    <<<dim3(32,8), 256>>>();
    final_k <<<8, 768>>>(out);
}

// round 10
// speedup vs baseline: 6.0236x; 1.0234x over previous
#include <cuda_runtime.h>
#include <cuda_bf16.h>
#include <cuda_fp16.h>
#include <cstdint>

#define NB 8
#define SEQ 2048
#define DIM 768
#define MTOT (NB*SEQ)                    // 16384
#define INV_SCALE 0.03608439182435161f   // 1/sqrt(768)

// ---- unified fp16 GEMM tiling: 128x128 CTA, 4 warps (2x2), 64x64 warp tiles ----
#define TM 128
#define TN 128
#define TKH 64                           // 64 halves = 128B per stage row
#define KTH (DIM/TKH)                    // 12
#define RSH 144                          // 128B data + 16B pad
#define AH_BYTES (TM*RSH)                // 18432
#define STAGE_H (2*AH_BYTES)             // 36864
#define NSTAGE 3
#define PTR_BYTES ((TM+TN)*8)
#define SMEM_DYN (NSTAGE*STAGE_H + PTR_BYTES)   // 112640

#define QS 8                             // colsum q-split

// ---------------- static device scratch (allocation-free) ----------------
__device__ float  g_Vc[(size_t)MTOT*DIM];            // compacted V rows (fp32)
__device__ __half g_Qh[(size_t)MTOT*DIM];            // Q fp16 (scaled)
__device__ __half g_Kh[(size_t)MTOT*DIM];            // compacted K fp16
__device__ __half g_xh[(size_t)MTOT*DIM];            // x fp16
__device__ __half g_Wh[3][DIM*DIM];                  // W fp16
__device__ __nv_bfloat16 g_P[(size_t)NB*SEQ*SEQ];    // P[q][kcol]
__device__ float g_Zpart[(size_t)MTOT*16];
__device__ float g_invZ[MTOT];
__device__ float g_cpart[NB*QS*SEQ];
__device__ float g_outpart[NB*32*DIM];
__device__ int   g_idx[NB*SEQ];
__device__ int   g_cnt[NB];

// ---------------- helpers ----------------
__device__ __forceinline__ uint32_t smem_u32(const void* p){
    uint32_t a;
    asm("{ .reg .u64 t; cvta.to.shared.u64 t, %1; cvt.u32.u64 %0, t; }" : "=r"(a) : "l"(p));
    return a;
}
__device__ __forceinline__ void cp16(uint32_t d, const void* s){
    asm volatile("cp.async.cg.shared.global [%0], [%1], 16;\n" :: "r"(d), "l"(s));
}
__device__ __forceinline__ void cp_commit(){ asm volatile("cp.async.commit_group;\n" ::); }
template<int N> __device__ __forceinline__ void cp_wait(){
    asm volatile("cp.async.wait_group %0;\n" :: "n"(N));
}
__device__ __forceinline__ void ldsm4(uint32_t addr, uint32_t* r){
    asm volatile("ldmatrix.sync.aligned.m8n8.x4.shared.b16 {%0,%1,%2,%3}, [%4];\n"
        : "=r"(r[0]), "=r"(r[1]), "=r"(r[2]), "=r"(r[3]) : "r"(addr));
}
// fp32-accumulate HMMA (rt~16) -- used only for V projection
__device__ __forceinline__ void mma_f16(float* c, const uint32_t* a, uint32_t b0, uint32_t b1){
    asm volatile("mma.sync.aligned.m16n8k16.row.col.f32.f16.f16.f32 "
        "{%0,%1,%2,%3},{%4,%5,%6,%7},{%8,%9},{%0,%1,%2,%3};\n"
        : "+f"(c[0]), "+f"(c[1]), "+f"(c[2]), "+f"(c[3])
        : "r"(a[0]), "r"(a[1]), "r"(a[2]), "r"(a[3]), "r"(b0), "r"(b1));
}
// fp16-accumulate HMMA (rt~8, 2x rate) -- Q/K proj + scores
__device__ __forceinline__ void mma_h16(uint32_t* c, const uint32_t* a, uint32_t b0, uint32_t b1){
    asm volatile("mma.sync.aligned.m16n8k16.row.col.f16.f16.f16.f16 "
        "{%0,%1},{%2,%3,%4,%5},{%6,%7},{%0,%1};\n"
        : "+r"(c[0]), "+r"(c[1])
        : "r"(a[0]), "r"(a[1]), "r"(a[2]), "r"(a[3]), "r"(b0), "r"(b1));
}

// ================= shared stage loader =================
__device__ __forceinline__ void issue_stage_h(uint32_t sb, int s, int k0,
        const __half* const* rowA, const __half* const* rowB, int t){
    uint32_t base = sb + s*STAGE_H;
#pragma unroll
    for (int j=0;j<8;j++){
        int ci = t + j*128; int r = ci>>3, c = ci&7;
        cp16(base + r*RSH + c*16, rowA[r] + k0 + c*8);
    }
    uint32_t bb = base + AH_BYTES;
#pragma unroll
    for (int j=0;j<8;j++){
        int ci = t + j*128; int r = ci>>3, c = ci&7;
        cp16(bb + r*RSH + c*16, rowB[r] + k0 + c*8);
    }
    cp_commit();
}

// ---- f16-acc compute path ----
__device__ __forceinline__ void compute_stage_h16(uint32_t sb, int s, int wm, int wn,
        uint32_t laneA, uint32_t laneB, uint32_t acc[4][8][2]){
    uint32_t aT = sb + s*STAGE_H + wm*64*RSH + laneA;
    uint32_t bT = sb + s*STAGE_H + AH_BYTES + wn*64*RSH + laneB;
#pragma unroll
    for (int kk=0; kk<4; kk++){
        uint32_t a[4][4], bb[4][4];
#pragma unroll
        for (int mf=0;mf<4;mf++) ldsm4(aT + mf*16*RSH + kk*32, a[mf]);
#pragma unroll
        for (int nf=0;nf<4;nf++) ldsm4(bT + nf*16*RSH + kk*32, bb[nf]);
#pragma unroll
        for (int mf=0;mf<4;mf++)
#pragma unroll
            for (int nf=0;nf<4;nf++){
                mma_h16(acc[mf][2*nf],   a[mf], bb[nf][0], bb[nf][1]);
                mma_h16(acc[mf][2*nf+1], a[mf], bb[nf][2], bb[nf][3]);
            }
    }
}

__device__ __forceinline__ void gemm_main_h16(uint32_t sb, const __half* const* rowA,
        const __half* const* rowB, int t, int wm, int wn,
        uint32_t laneA, uint32_t laneB, uint32_t acc[4][8][2]){
    issue_stage_h(sb, 0, 0,   rowA, rowB, t);
    issue_stage_h(sb, 1, TKH, rowA, rowB, t);
#pragma unroll 1
    for (int it=0; it<KTH; ++it){
        if (it < KTH-1) cp_wait<1>(); else cp_wait<0>();
        __syncthreads();
        if (it+2 < KTH) issue_stage_h(sb, (it+2)%NSTAGE, (it+2)*TKH, rowA, rowB, t);
        compute_stage_h16(sb, it%NSTAGE, wm, wn, laneA, laneB, acc);
    }
}

// ---- f32-acc compute path (V only) ----
__device__ __forceinline__ void compute_stage_h32(uint32_t sb, int s, int wm, int wn,
        uint32_t laneA, uint32_t laneB, float acc[4][8][4]){
    uint32_t aT = sb + s*STAGE_H + wm*64*RSH + laneA;
    uint32_t bT = sb + s*STAGE_H + AH_BYTES + wn*64*RSH + laneB;
#pragma unroll
    for (int kk=0; kk<4; kk++){
        uint32_t a[4][4], bb[4][4];
#pragma unroll
        for (int mf=0;mf<4;mf++) ldsm4(aT + mf*16*RSH + kk*32, a[mf]);
#pragma unroll
        for (int nf=0;nf<4;nf++) ldsm4(bT + nf*16*RSH + kk*32, bb[nf]);
#pragma unroll
        for (int mf=0;mf<4;mf++)
#pragma unroll
            for (int nf=0;nf<4;nf++){
                mma_f16(acc[mf][2*nf],   a[mf], bb[nf][0], bb[nf][1]);
                mma_f16(acc[mf][2*nf+1], a[mf], bb[nf][2], bb[nf][3]);
            }
    }
}

__device__ __forceinline__ void gemm_main_h32(uint32_t sb, const __half* const* rowA,
        const __half* const* rowB, int t, int wm, int wn,
        uint32_t laneA, uint32_t laneB, float acc[4][8][4]){
    issue_stage_h(sb, 0, 0,   rowA, rowB, t);
    issue_stage_h(sb, 1, TKH, rowA, rowB, t);
#pragma unroll 1
    for (int it=0; it<KTH; ++it){
        if (it < KTH-1) cp_wait<1>(); else cp_wait<0>();
        __syncthreads();
        if (it+2 < KTH) issue_stage_h(sb, (it+2)%NSTAGE, (it+2)*TKH, rowA, rowB, t);
        compute_stage_h32(sb, it%NSTAGE, wm, wn, laneA, laneB, acc);
    }
}

// ---------------- kernel A: fp16 conversion ----------------
__global__ void round_k(const float* __restrict__ x, const float* __restrict__ Wq,
                        const float* __restrict__ Wk, const float* __restrict__ Wv){
    size_t i = ((size_t)blockIdx.x*256 + threadIdx.x)*4;
    if (i < (size_t)MTOT*DIM){
        float4 v = *(const float4*)(x+i);
        *(__half2*)(g_xh+i)   = __floats2half2_rn(v.x, v.y);
        *(__half2*)(g_xh+i+2) = __floats2half2_rn(v.z, v.w);
    }
    if (i < (size_t)DIM*DIM){
        float4 q = *(const float4*)(Wq+i);
        *(__half2*)(&g_Wh[0][i])   = __floats2half2_rn(q.x,q.y);
        *(__half2*)(&g_Wh[0][i+2]) = __floats2half2_rn(q.z,q.w);
        float4 k = *(const float4*)(Wk+i);
        *(__half2*)(&g_Wh[1][i])   = __floats2half2_rn(k.x,k.y);
        *(__half2*)(&g_Wh[1][i+2]) = __floats2half2_rn(k.z,k.w);
        float4 w = *(const float4*)(Wv+i);
        *(__half2*)(&g_Wh[2][i])   = __floats2half2_rn(w.x,w.y);
        *(__half2*)(&g_Wh[2][i+2]) = __floats2half2_rn(w.z,w.w);
    }
}

// ---------------- kernel B: mask prefix-scan -> compact index list ----------------
__global__ void prep_k(const int* __restrict__ mask){
    int b = blockIdx.x, t = threadIdx.x;
    __shared__ int sm[SEQ];
    __shared__ int ws[8];
    for (int i=t;i<SEQ;i+=256) sm[i] = mask[b*SEQ+i];
    __syncthreads();
    int base_i = t*8;
    int loc[8], s=0;
#pragma unroll
    for (int j=0;j<8;j++){ loc[j]=s; s += sm[base_i+j]; }
    int lane = t&31, w = t>>5;
    int v = s;
#pragma unroll
    for (int off=1; off<32; off<<=1){
        int n = __shfl_up_sync(0xffffffffu, v, off);
        if (lane >= off) v += n;
    }
    if (lane==31) ws[w] = v;
    __syncthreads();
    int wbase = 0;
#pragma unroll
    for (int i=0;i<8;i++) if (i<w) wbase += ws[i];
    int excl = wbase + v - s;
#pragma unroll
    for (int j=0;j<8;j++)
        if (sm[base_i+j]) g_idx[b*SEQ + excl + loc[j]] = base_i+j;
    if (t==255) g_cnt[b] = wbase + v;
}

// ---------------- kernel C: fused Q/K/V projections ----------------
// grid = (6, 384): y<128 -> Q; 128..255 -> K; 256..383 -> V. block = 128.
// Q/K use fp16 accumulators (2x HMMA rate); V uses fp32 accumulators.
__global__ void __launch_bounds__(128,2) proj_k(const float* __restrict__ bq,
        const float* __restrict__ bk, const float* __restrict__ bv){
    extern __shared__ __align__(16) char dsm[];
    uint32_t sb = smem_u32(dsm);
    const __half** rowA = (const __half**)(dsm + NSTAGE*STAGE_H);
    const __half** rowB = rowA + TM;
    int t = threadIdx.x, L = t&31, w = t>>5;
    int wm = w&1, wn = w>>1;
    int y = blockIdx.y;
    int proj = (y < 128) ? 0 : ((y < 256) ? 1 : 2);
    int nBase = blockIdx.x*TN;

    int mBase, b = 0;
    if (proj == 0){
        mBase = y*TM;
    } else {
        int i = y - (proj==1 ? 128 : 256);
        b = i >> 4;
        mBase = (i & 15)*TM;
        int cnt = g_cnt[b];
        int cntp = ((cnt + 127) >> 7) << 7;
        if (mBase >= cntp) return;
    }
    if (proj == 0){
        rowA[t] = g_xh + (size_t)(mBase + t)*DIM;
    } else {
        int cnt = g_cnt[b];
        int j = mBase + t; if (j >= cnt) j = cnt-1;
        rowA[t] = g_xh + ((size_t)b*SEQ + g_idx[b*SEQ + j])*DIM;
    }
    rowB[t] = g_Wh[proj] + (size_t)(nBase + t)*DIM;
    __syncthreads();

    uint32_t laneA = (L&15)*RSH + ((L>>4)&1)*16;
    uint32_t laneB = ((L&7) + ((L>>4)&1)*8)*RSH + ((L>>3)&1)*16;
    int gq = L>>2, tig = L&3;

    if (proj < 2){
        uint32_t acc[4][8][2] = {};
        gemm_main_h16(sb, rowA, rowB, t, wm, wn, laneA, laneB, acc);
        const float* bias = proj==0 ? bq : bk;
        float scale = proj==0 ? INV_SCALE : 1.0f;
        __half* out = (proj==0) ? g_Qh : (g_Kh + (size_t)b*SEQ*DIM);
#pragma unroll
        for (int mf=0;mf<4;mf++){
            int r0 = mBase + wm*64 + mf*16 + gq;
#pragma unroll
            for (int j=0;j<8;j++){
                int col = nBase + wn*64 + (j>>1)*16 + (j&1)*8 + tig*2;
                float b0 = bias[col], b1 = bias[col+1];
                float2 lo = __half22float2(*(__half2*)&acc[mf][j][0]);
                float2 hi = __half22float2(*(__half2*)&acc[mf][j][1]);
                float x0 = (lo.x+b0)*scale, x1 = (lo.y+b1)*scale;
                float x2 = (hi.x+b0)*scale, x3 = (hi.y+b1)*scale;
                *(__half2*)&out[(size_t)r0*DIM + col]     = __floats2half2_rn(x0,x1);
                *(__half2*)&out[(size_t)(r0+8)*DIM + col] = __floats2half2_rn(x2,x3);
            }
        }
    } else {
        float acc[4][8][4] = {};
        gemm_main_h32(sb, rowA, rowB, t, wm, wn, laneA, laneB, acc);
        float* out = g_Vc + (size_t)b*SEQ*DIM;
#pragma unroll
        for (int mf=0;mf<4;mf++){
            int r0 = mBase + wm*64 + mf*16 + gq;
#pragma unroll
            for (int j=0;j<8;j++){
                int col = nBase + wn*64 + (j>>1)*16 + (j&1)*8 + tig*2;
                float b0 = bv[col], b1 = bv[col+1];
                *(float2*)&out[(size_t)r0*DIM + col]     = make_float2(acc[mf][j][0]+b0, acc[mf][j][1]+b1);
                *(float2*)&out[(size_t)(r0+8)*DIM + col] = make_float2(acc[mf][j][2]+b0, acc[mf][j][3]+b1);
            }
        }
    }
}

// ---------------- kernel D: scores (fp16 acc) + exp + mask + Z partials ----------------
__global__ void __launch_bounds__(128,2) scores_k(){
    int b = blockIdx.z;
    int cnt = g_cnt[b];
    int cntp = ((cnt + 127) >> 7) << 7;
    int nBase = blockIdx.x*TN;
    if (nBase >= cntp) return;
    int mBase = blockIdx.y*TM;
    extern __shared__ __align__(16) char dsm[];
    uint32_t sb = smem_u32(dsm);
    const __half** rowA = (const __half**)(dsm + NSTAGE*STAGE_H);
    const __half** rowB = rowA + TM;
    float* sRow = (float*)dsm;                  // reused after mainloop
    int t = threadIdx.x, L = t&31, w = t>>5;
    int wm = w&1, wn = w>>1;
    rowA[t] = g_Qh + ((size_t)b*SEQ + mBase + t)*DIM;
    rowB[t] = g_Kh + ((size_t)b*SEQ + nBase + t)*DIM;
    __syncthreads();
    uint32_t laneA = (L&15)*RSH + ((L>>4)&1)*16;
    uint32_t laneB = ((L&7) + ((L>>4)&1)*8)*RSH + ((L>>3)&1)*16;
    uint32_t acc[4][8][2] = {};
    gemm_main_h16(sb, rowA, rowB, t, wm, wn, laneA, laneB, acc);

    int gq = L>>2, tig = L&3;
    __nv_bfloat16* P = g_P + (size_t)b*SEQ*SEQ;
    float zl[4] = {0,0,0,0}, zh[4] = {0,0,0,0};
#pragma unroll
    for (int mf=0;mf<4;mf++){
        int q0 = mBase + wm*64 + mf*16 + gq;
#pragma unroll
        for (int j=0;j<8;j++){
            int kcol = nBase + wn*64 + (j>>1)*16 + (j&1)*8 + tig*2;
            float2 lo = __half22float2(*(__half2*)&acc[mf][j][0]);
            float2 hi = __half22float2(*(__half2*)&acc[mf][j][1]);
            float p0 = (kcol   < cnt) ? __expf(lo.x) : 0.f;
            float p1 = (kcol+1 < cnt) ? __expf(lo.y) : 0.f;
            float p2 = (kcol   < cnt) ? __expf(hi.x) : 0.f;
            float p3 = (kcol+1 < cnt) ? __expf(hi.y) : 0.f;
            *(__nv_bfloat162*)&P[(size_t)q0*SEQ + kcol]     = __floats2bfloat162_rn(p0,p1);
            *(__nv_bfloat162*)&P[(size_t)(q0+8)*SEQ + kcol] = __floats2bfloat162_rn(p2,p3);
            zl[mf] += p0+p1; zh[mf] += p2+p3;
        }
    }
    __syncthreads();   // stage buffers done; reuse as sRow
#pragma unroll
    for (int mf=0;mf<4;mf++){
        float x0 = zl[mf];
        x0 += __shfl_xor_sync(0xffffffffu, x0, 1);
        x0 += __shfl_xor_sync(0xffffffffu, x0, 2);
        float x1 = zh[mf];
        x1 += __shfl_xor_sync(0xffffffffu, x1, 1);
        x1 += __shfl_xor_sync(0xffffffffu, x1, 2);
        if (tig==0){
            sRow[(wm*64 + mf*16 + gq)*2     + wn] = x0;
            sRow[(wm*64 + mf*16 + gq + 8)*2 + wn] = x1;
        }
    }
    __syncthreads();
    if (t < TM){
        float z = sRow[t*2] + sRow[t*2+1];
        g_Zpart[((size_t)b*SEQ + mBase + t)*16 + blockIdx.x] = z;
    }
}

// ---------------- kernel E: Z reduce ----------------
__global__ void zred_k(){
    int i = blockIdx.x*256 + threadIdx.x;
    if (i < MTOT){
        int b = i >> 11;
        int nt = (g_cnt[b] + 127) >> 7;
        float s = 0.f;
        for (int j=0;j<nt;j++) s += g_Zpart[(size_t)i*16 + j];
        g_invZ[i] = 1.0f/s;
    }
}

// ---------------- kernel F: cpart[b][qc][k] = sum_{q in chunk} P[q][k]*invZ[q] --------
__global__ void __launch_bounds__(256) colsum_k(){
    int b = blockIdx.y, qc = blockIdx.z;
    int cnt = g_cnt[b];
    int cntp = ((cnt + 127) >> 7) << 7;
    int k = blockIdx.x*256 + threadIdx.x;
    float* dst = g_cpart + ((size_t)(b*QS + qc))*SEQ;
    if (blockIdx.x*256 >= cntp){ dst[k] = 0.f; return; }
    __shared__ float sz[SEQ/QS];
    int qBase = qc*(SEQ/QS);
    for (int i=threadIdx.x; i<SEQ/QS; i+=256) sz[i] = g_invZ[b*SEQ + qBase + i];
    __syncthreads();
    const __nv_bfloat16* P = g_P + (size_t)b*SEQ*SEQ + (size_t)qBase*SEQ + k;
    float a0=0.f, a1=0.f, a2=0.f, a3=0.f;
#pragma unroll 4
    for (int q=0; q<SEQ/QS; q+=4){
        a0 += __bfloat162float(P[(size_t)(q+0)*SEQ]) * sz[q+0];
        a1 += __bfloat162float(P[(size_t)(q+1)*SEQ]) * sz[q+1];
        a2 += __bfloat162float(P[(size_t)(q+2)*SEQ]) * sz[q+2];
        a3 += __bfloat162float(P[(size_t)(q+3)*SEQ]) * sz[q+3];
    }
    dst[k] = (a0+a1)+(a2+a3);
}

// ---------------- kernel G: partial out = c @ Vc ----------------
__global__ void __launch_bounds__(256) cv_k(){
    int b  = blockIdx.y;
    int kc = blockIdx.x*64;
    int cnt = g_cnt[b];
    int cntp = ((cnt + 127) >> 7) << 7;
    float* op = g_outpart + ((size_t)b*32 + blockIdx.x)*DIM;
    int o = threadIdx.x;
    if (kc >= cntp){ op[o]=0.f; op[o+256]=0.f; op[o+512]=0.f; return; }
    __shared__ float sc[64];
    if (threadIdx.x < 64){
        float s = 0.f;
#pragma unroll
        for (int qc=0;qc<QS;qc++)
            s += g_cpart[((size_t)(b*QS + qc))*SEQ + kc + threadIdx.x];
        sc[threadIdx.x] = s;
    }
    __syncthreads();
    const float* V = g_Vc + ((size_t)b*SEQ + kc)*DIM;
    float a0=0.f, a1=0.f, a2=0.f;
    for (int k=0;k<64;k++){
        float cv = sc[k];
        const float* vr = V + (size_t)k*DIM;
        a0 += cv*vr[o]; a1 += cv*vr[o+256]; a2 += cv*vr[o+512];
    }
    op[o]=a0; op[o+256]=a1; op[o+512]=a2;
}

// ---------------- kernel H: final reduce + mean ----------------
__global__ void final_k(float* __restrict__ out){
    int b = blockIdx.x, o = threadIdx.x;
    float s = 0.f;
#pragma unroll
    for (int c=0;c<32;c++) s += g_outpart[((size_t)b*32 + c)*DIM + o];
    out[b*DIM + o] = s * (1.0f/(float)SEQ);
}

// ---------------- launch ----------------
extern "C" void kernel_launch(void* const* d_in, const int* in_sizes, int n_in,
                              void* d_out, int out_size){
    const float* x    = (const float*)d_in[0];
    const int*   mask = (const int*)  d_in[1];
    const float* Wq   = (const float*)d_in[2];
    const float* bq   = (const float*)d_in[3];
    const float* Wk   = (const float*)d_in[4];
    const float* bk   = (const float*)d_in[5];
    const float* Wv   = (const float*)d_in[6];
    const float* bv   = (const float*)d_in[7];
    float* out = (float*)d_out;

    cudaFuncSetAttribute(proj_k,   cudaFuncAttributeMaxDynamicSharedMemorySize, SMEM_DYN);
    cudaFuncSetAttribute(scores_k, cudaFuncAttributeMaxDynamicSharedMemorySize, SMEM_DYN);

    round_k <<<(MTOT*DIM/4 + 255)/256, 256>>>(x, Wq, Wk, Wv);
    prep_k  <<<NB, 256>>>(mask);
    proj_k  <<<dim3(6,384),   128, SMEM_DYN>>>(bq, bk, bv);
    scores_k<<<dim3(16,16,8), 128, SMEM_DYN>>>();
    zred_k  <<<64, 256>>>();
    colsum_k<<<dim3(8,8,QS), 256>>>();
    cv_k    <<<dim3(32,8), 256>>>();
    final_k <<<8, 768>>>(out);
}